// round 9
// baseline (speedup 1.0000x reference)
#include <cuda_runtime.h>
#include <cuda_fp16.h>
#include <math.h>
#include <stdint.h>

// ---------------------------------------------------------------------------
// Problem constants
// ---------------------------------------------------------------------------
#define B_ 2
#define NV 4
#define H_ 240
#define W_ 240
#define H1_ 120
#define W1_ 120
#define D_ 32
#define NPB 131072
#define PT (B_ * NPB)
#define INBASE 70
#define XPAD_H 80             // padded fp16 feature row (160 B)
#define DH 128
#define TM 128
#define MLP_THREADS 512

#define ACT_W 136             // halves per act row (272 B, conflict-free)
#define ACT_W32 68
#define WS_W 136
#define WS_W32 68
#define ACT_BYTES (128 * ACT_W * 2)
#define WS_BYTES  (128 * WS_W * 2)

// ---------------------------------------------------------------------------
// Scratch (device globals)
// ---------------------------------------------------------------------------
__device__ __half g_xh[(size_t)PT * XPAD_H];
__device__ __half g_featsTh[(size_t)B_ * NV * H1_ * W1_ * D_]; // channel-last fp16 feats
__device__ __half g_imgsTh[(size_t)B_ * NV * H_ * W_ * 3];     // channel-last fp16 imgs
__device__ float  g_proj[B_ * NV * 12];
__device__ __half g_wpadh[5 * 128 * WS_W];

// ---------------------------------------------------------------------------
// helpers
// ---------------------------------------------------------------------------
__device__ __forceinline__ void mma_f16(float (&d)[4], const uint32_t (&a)[4],
                                        const uint32_t (&b)[2]) {
    asm volatile(
        "mma.sync.aligned.m16n8k16.row.col.f32.f16.f16.f32 "
        "{%0,%1,%2,%3}, {%4,%5,%6,%7}, {%8,%9}, {%0,%1,%2,%3};"
        : "+f"(d[0]), "+f"(d[1]), "+f"(d[2]), "+f"(d[3])
        : "r"(a[0]), "r"(a[1]), "r"(a[2]), "r"(a[3]), "r"(b[0]), "r"(b[1]));
}

__device__ __forceinline__ uint32_t smem_u32(const void* p) {
    return (uint32_t)__cvta_generic_to_shared(p);
}

__device__ __forceinline__ void cp16(uint32_t saddr, const void* g) {
    asm volatile("cp.async.cg.shared.global [%0], [%1], 16;" :: "r"(saddr), "l"(g));
}
#define CP_COMMIT() asm volatile("cp.async.commit_group;")
#define CP_WAIT(N)  asm volatile("cp.async.wait_group %0;" :: "n"(N))

// 8 halves (one uint4) -> 8 floats
__device__ __forceinline__ void h8_to_f(const uint4& u, float* f) {
    const __half2* h = reinterpret_cast<const __half2*>(&u);
#pragma unroll
    for (int i = 0; i < 4; i++) {
        float2 v = __half22float2(h[i]);
        f[i * 2 + 0] = v.x;
        f[i * 2 + 1] = v.y;
    }
}

// ---------------------------------------------------------------------------
// Kernel 0: projection matrices  P = K @ inv(c2w)[0:3, :]
// ---------------------------------------------------------------------------
__global__ void proj_kernel(const float* __restrict__ cams) {
    int i = threadIdx.x;
    if (i >= B_ * NV) return;
    const float* c = cams + i * 27;
    float K[9];
#pragma unroll
    for (int j = 0; j < 9; j++) K[j] = c[2 + j];
    float m[16];
#pragma unroll
    for (int j = 0; j < 16; j++) m[j] = c[11 + j];

    float inv[16];
    inv[0]  =  m[5]*m[10]*m[15] - m[5]*m[11]*m[14] - m[9]*m[6]*m[15] + m[9]*m[7]*m[14] + m[13]*m[6]*m[11] - m[13]*m[7]*m[10];
    inv[4]  = -m[4]*m[10]*m[15] + m[4]*m[11]*m[14] + m[8]*m[6]*m[15] - m[8]*m[7]*m[14] - m[12]*m[6]*m[11] + m[12]*m[7]*m[10];
    inv[8]  =  m[4]*m[9]*m[15]  - m[4]*m[11]*m[13] - m[8]*m[5]*m[15] + m[8]*m[7]*m[13] + m[12]*m[5]*m[11] - m[12]*m[7]*m[9];
    inv[12] = -m[4]*m[9]*m[14]  + m[4]*m[10]*m[13] + m[8]*m[5]*m[14] - m[8]*m[6]*m[13] - m[12]*m[5]*m[10] + m[12]*m[6]*m[9];
    inv[1]  = -m[1]*m[10]*m[15] + m[1]*m[11]*m[14] + m[9]*m[2]*m[15] - m[9]*m[3]*m[14] - m[13]*m[2]*m[11] + m[13]*m[3]*m[10];
    inv[5]  =  m[0]*m[10]*m[15] - m[0]*m[11]*m[14] - m[8]*m[2]*m[15] + m[8]*m[3]*m[14] + m[12]*m[2]*m[11] - m[12]*m[3]*m[10];
    inv[9]  = -m[0]*m[9]*m[15]  + m[0]*m[11]*m[13] + m[8]*m[1]*m[15] - m[8]*m[3]*m[13] - m[12]*m[1]*m[11] + m[12]*m[3]*m[9];
    inv[13] =  m[0]*m[9]*m[14]  - m[0]*m[10]*m[13] - m[8]*m[1]*m[14] + m[8]*m[2]*m[13] + m[12]*m[1]*m[10] - m[12]*m[2]*m[9];
    inv[2]  =  m[1]*m[6]*m[15]  - m[1]*m[7]*m[14]  - m[5]*m[2]*m[15] + m[5]*m[3]*m[14] + m[13]*m[2]*m[7]  - m[13]*m[3]*m[6];
    inv[6]  = -m[0]*m[6]*m[15]  + m[0]*m[7]*m[14]  + m[4]*m[2]*m[15] - m[4]*m[3]*m[14] - m[12]*m[2]*m[7]  + m[12]*m[3]*m[6];
    inv[10] =  m[0]*m[5]*m[15]  - m[0]*m[7]*m[13]  - m[4]*m[1]*m[15] + m[4]*m[3]*m[13] + m[12]*m[1]*m[7]  - m[12]*m[3]*m[5];
    inv[14] = -m[0]*m[5]*m[14]  + m[0]*m[6]*m[13]  + m[4]*m[1]*m[14] - m[4]*m[2]*m[13] - m[12]*m[1]*m[6]  + m[12]*m[2]*m[5];
    inv[3]  = -m[1]*m[6]*m[11]  + m[1]*m[7]*m[10]  + m[5]*m[2]*m[11] - m[5]*m[3]*m[10] - m[9]*m[2]*m[7]   + m[9]*m[3]*m[6];
    inv[7]  =  m[0]*m[6]*m[11]  - m[0]*m[7]*m[10]  - m[4]*m[2]*m[11] + m[4]*m[3]*m[10] + m[8]*m[2]*m[7]   - m[8]*m[3]*m[6];
    inv[11] = -m[0]*m[5]*m[11]  + m[0]*m[7]*m[9]   + m[4]*m[1]*m[11] - m[4]*m[3]*m[9]  - m[8]*m[1]*m[7]   + m[8]*m[3]*m[5];
    inv[15] =  m[0]*m[5]*m[10]  - m[0]*m[6]*m[9]   - m[4]*m[1]*m[10] + m[4]*m[2]*m[9]  + m[8]*m[1]*m[6]   - m[8]*m[2]*m[5];

    float det = m[0]*inv[0] + m[1]*inv[4] + m[2]*inv[8] + m[3]*inv[12];
    float id = 1.0f / det;
#pragma unroll
    for (int j = 0; j < 16; j++) inv[j] *= id;

#pragma unroll
    for (int r = 0; r < 3; r++) {
#pragma unroll
        for (int cc = 0; cc < 4; cc++) {
            float s = K[r*3+0]*inv[0*4+cc] + K[r*3+1]*inv[1*4+cc] + K[r*3+2]*inv[2*4+cc];
            g_proj[i*12 + r*4 + cc] = s;
        }
    }
}

// ---------------------------------------------------------------------------
// Weight prep: fp16, transposed [l][n][k]
// ---------------------------------------------------------------------------
__global__ void wprep_kernel(const float* __restrict__ w0, const float* __restrict__ w1,
                             const float* __restrict__ w2, const float* __restrict__ w3,
                             const float* __restrict__ w4) {
    int o = blockIdx.x * blockDim.x + threadIdx.x;
    if (o >= 5 * 128 * WS_W) return;
    int l = o / (128 * WS_W);
    int rem = o - l * 128 * WS_W;
    int n = rem / WS_W;
    int k = rem - n * WS_W;
    float v = 0.f;
    if (l == 0) {
        if (k < INBASE) v = w0[k * DH + n];
    } else if (k < DH) {
        const float* w = (l == 1) ? w1 : (l == 2) ? w2 : (l == 3) ? w3 : w4;
        v = w[k * DH + n];
    }
    g_wpadh[o] = __float2half_rn(v);
}

// ---------------------------------------------------------------------------
// Transposes to channel-last fp16
// ---------------------------------------------------------------------------
__global__ void tfeat_kernel(const float* __restrict__ f) {
    int o = blockIdx.x * blockDim.x + threadIdx.x;
    if (o >= B_ * NV * H1_ * W1_ * D_) return;
    int c = o & (D_ - 1);
    int rest = o >> 5;
    int x = rest % W1_;
    int t2 = rest / W1_;
    int y = t2 % H1_;
    int bv = t2 / H1_;
    g_featsTh[o] = __float2half_rn(f[((size_t)(bv * D_ + c)) * (H1_ * W1_) + y * W1_ + x]);
}

__global__ void timg_kernel(const float* __restrict__ im) {
    int o = blockIdx.x * blockDim.x + threadIdx.x;
    if (o >= B_ * NV * H_ * W_ * 3) return;
    int c = o % 3;
    int rest = o / 3;
    int x = rest % W_;
    int t2 = rest / W_;
    int y = t2 % H_;
    int bv = t2 / H_;
    g_imgsTh[o] = __float2half_rn(im[((size_t)(bv * 3 + c)) * (H_ * W_) + y * W_ + x]);
}

// ---------------------------------------------------------------------------
// Kernel 1: quad featurize (4 threads/point), fp16 taps -> g_xh [PT][80]
// ---------------------------------------------------------------------------
__global__ void __launch_bounds__(256) featurize_kernel(const float* __restrict__ xyz) {
    int t = blockIdx.x * blockDim.x + threadIdx.x;
    int gp = t >> 2;
    int q  = t & 3;
    if (gp >= PT) return;
    int b = gp / NPB;

    float X = xyz[(size_t)gp * 3 + 0];
    float Y = xyz[(size_t)gp * 3 + 1];
    float Z = xyz[(size_t)gp * 3 + 2];

    float fs[8], fq[8];
#pragma unroll
    for (int i = 0; i < 8; i++) { fs[i] = 0.f; fq[i] = 0.f; }
    float rs = 0.f, rq = 0.f;
    float s = 0.f;

    const float SX = (float)(W1_ - 1) / (float)(W_ - 1);
    const float SY = (float)(H1_ - 1) / (float)(H_ - 1);

#pragma unroll
    for (int v = 0; v < NV; v++) {
        const float* Pm = &g_proj[(b * NV + v) * 12];
        float pxn = Pm[0]*X + Pm[1]*Y + Pm[2]*Z  + Pm[3];
        float pyn = Pm[4]*X + Pm[5]*Y + Pm[6]*Z  + Pm[7];
        float pz  = Pm[8]*X + Pm[9]*Y + Pm[10]*Z + Pm[11];
        float d = fmaxf(pz, 1e-8f);
        float px = pxn / d;
        float py = pyn / d;
        bool inb = (pz > 1e-4f) && (px >= 0.f) && (px <= (float)(W_ - 1))
                                && (py >= 0.f) && (py <= (float)(H_ - 1));
        if (!inb) continue;
        s += 1.f;

        if (q < 3) {
            float x0f = floorf(px), y0f = floorf(py);
            float wx = px - x0f, wy = py - y0f;
            int x0 = (int)x0f;
            int y0 = (int)y0f;
            int x1 = min(x0 + 1, W_ - 1);
            int y1 = min(y0 + 1, H_ - 1);
            float w00 = (1.f - wx) * (1.f - wy);
            float w01 = wx * (1.f - wy);
            float w10 = (1.f - wx) * wy;
            float w11 = wx * wy;
            const __half* ib = g_imgsTh + (size_t)(b * NV + v) * H_ * W_ * 3 + q;
            float val = __half2float(ib[(size_t)(y0 * W_ + x0) * 3]) * w00
                      + __half2float(ib[(size_t)(y0 * W_ + x1) * 3]) * w01
                      + __half2float(ib[(size_t)(y1 * W_ + x0) * 3]) * w10
                      + __half2float(ib[(size_t)(y1 * W_ + x1) * 3]) * w11;
            rs += val;
            rq += val * val;
        }

        {
            float fx = px * SX;
            float fy = py * SY;
            float x0f = floorf(fx), y0f = floorf(fy);
            float wx = fx - x0f, wy = fy - y0f;
            int x0 = (int)x0f;
            int y0 = (int)y0f;
            int x1 = min(x0 + 1, W1_ - 1);
            int y1 = min(y0 + 1, H1_ - 1);
            float w00 = (1.f - wx) * (1.f - wy);
            float w01 = wx * (1.f - wy);
            float w10 = (1.f - wx) * wy;
            float w11 = wx * wy;
            const __half* fb = g_featsTh + (size_t)(b * NV + v) * H1_ * W1_ * D_ + q * 8;
            uint4 u00 = *reinterpret_cast<const uint4*>(fb + (size_t)(y0 * W1_ + x0) * D_);
            uint4 u01 = *reinterpret_cast<const uint4*>(fb + (size_t)(y0 * W1_ + x1) * D_);
            uint4 u10 = *reinterpret_cast<const uint4*>(fb + (size_t)(y1 * W1_ + x0) * D_);
            uint4 u11 = *reinterpret_cast<const uint4*>(fb + (size_t)(y1 * W1_ + x1) * D_);
            float a[8], bb[8], cc[8], dd[8];
            h8_to_f(u00, a); h8_to_f(u01, bb); h8_to_f(u10, cc); h8_to_f(u11, dd);
#pragma unroll
            for (int j = 0; j < 8; j++) {
                float vv = a[j]*w00 + bb[j]*w01 + cc[j]*w10 + dd[j]*w11;
                fs[j] += vv;
                fq[j] += vv * vv;
            }
        }
    }

    float denom = s + 1e-6f;
    float invd = 1.f / denom;
    float alpha = s * invd;
    float two_m_a = 2.f - alpha;
    __half* xo = g_xh + (size_t)gp * XPAD_H;

    if (q < 3) {
        float m  = rs * invd;
        float e2 = rq * invd;
        xo[q]      = __float2half_rn(m);
        xo[35 + q] = __float2half_rn(e2 - two_m_a * m * m);
    }
#pragma unroll
    for (int j = 0; j < 8; j++) {
        int i = 3 + q * 8 + j;
        float m  = fs[j] * invd;
        float e2 = fq[j] * invd;
        xo[i]      = __float2half_rn(m);
        xo[35 + i] = __float2half_rn(e2 - two_m_a * m * m);
    }
    if (q == 0) {
#pragma unroll
        for (int j = 70; j < XPAD_H; j++) xo[j] = __float2half_rn(0.f);
    }
}

// ---------------------------------------------------------------------------
// Kernel 2: fused MLP, fp16 mma.m16n8k16, 512 threads, 2 blocks/SM
// ---------------------------------------------------------------------------
template <int KSTEPS>
__device__ __forceinline__ void mma_gemm(const uint32_t* __restrict__ act32,
                                         const uint32_t* __restrict__ ws32,
                                         float (&acc)[2][4][4],
                                         int lane, int m_blk, int n_blk) {
#pragma unroll
    for (int mi = 0; mi < 2; mi++)
#pragma unroll
        for (int ni = 0; ni < 4; ni++)
#pragma unroll
            for (int j = 0; j < 4; j++) acc[mi][ni][j] = 0.f;

    const int r = lane >> 2;
    const int cp = lane & 3;

#pragma unroll
    for (int kt = 0; kt < KSTEPS; kt++) {
        const int k32 = kt * 8;
        uint32_t a[2][4];
#pragma unroll
        for (int mi = 0; mi < 2; mi++) {
            const int base = (m_blk * 32 + mi * 16 + r) * ACT_W32 + k32 + cp;
            a[mi][0] = act32[base];
            a[mi][1] = act32[base + 8 * ACT_W32];
            a[mi][2] = act32[base + 4];
            a[mi][3] = act32[base + 8 * ACT_W32 + 4];
        }
        uint32_t bf[4][2];
#pragma unroll
        for (int ni = 0; ni < 4; ni++) {
            const int n = n_blk * 32 + ni * 8 + r;
            const int bbase = n * WS_W32 + k32 + cp;
            bf[ni][0] = ws32[bbase];
            bf[ni][1] = ws32[bbase + 4];
        }
#pragma unroll
        for (int mi = 0; mi < 2; mi++)
#pragma unroll
            for (int ni = 0; ni < 4; ni++)
                mma_f16(acc[mi][ni], a[mi], bf[ni]);
    }
}

__device__ __forceinline__ void epilogue(uint32_t* __restrict__ act32,
                                         const float* __restrict__ bs,
                                         float (&acc)[2][4][4],
                                         int lane, int m_blk, int n_blk,
                                         bool leaky) {
    const int r = lane >> 2;
    const int cp = lane & 3;
#pragma unroll
    for (int mi = 0; mi < 2; mi++) {
        const int row0 = m_blk * 32 + mi * 16 + r;
#pragma unroll
        for (int ni = 0; ni < 4; ni++) {
            const int col = n_blk * 32 + ni * 8 + cp * 2;
            float v0 = acc[mi][ni][0] + bs[col];
            float v1 = acc[mi][ni][1] + bs[col + 1];
            float v2 = acc[mi][ni][2] + bs[col];
            float v3 = acc[mi][ni][3] + bs[col + 1];
            if (leaky) {
                v0 = v0 > 0.f ? v0 : 0.01f * v0;
                v1 = v1 > 0.f ? v1 : 0.01f * v1;
                v2 = v2 > 0.f ? v2 : 0.01f * v2;
                v3 = v3 > 0.f ? v3 : 0.01f * v3;
            }
            __half2 h01 = __halves2half2(__float2half_rn(v0), __float2half_rn(v1));
            __half2 h23 = __halves2half2(__float2half_rn(v2), __float2half_rn(v3));
            act32[row0 * ACT_W32 + col / 2]       = *reinterpret_cast<uint32_t*>(&h01);
            act32[(row0 + 8) * ACT_W32 + col / 2] = *reinterpret_cast<uint32_t*>(&h23);
        }
    }
}

__global__ void __launch_bounds__(MLP_THREADS, 2) mlp_mma_kernel(
    const float* __restrict__ b0, const float* __restrict__ b1,
    const float* __restrict__ b2, const float* __restrict__ b3,
    const float* __restrict__ b4,
    const float* __restrict__ w5, const float* __restrict__ b5,
    const float* __restrict__ dw, const float* __restrict__ db,
    float* __restrict__ out) {

    extern __shared__ char smem[];
    uint32_t* act32 = reinterpret_cast<uint32_t*>(smem);
    uint32_t* wbuf32 = reinterpret_cast<uint32_t*>(smem + ACT_BYTES);
    float* bias = reinterpret_cast<float*>(smem + ACT_BYTES + 2 * WS_BYTES);
    float* w5s  = bias + 5 * DH;
    float* dws  = w5s + DH * 3;
    const __half* act_h = reinterpret_cast<const __half*>(smem);

    const int tid  = threadIdx.x;
    const int lane = tid & 31;
    const int warp = tid >> 5;
    const int m_blk = warp & 3;
    const int n_blk = warp >> 2;
    const int p0 = blockIdx.x * TM;

    const uint32_t s_act = smem_u32(act32);
    const uint32_t s_wb0 = smem_u32(wbuf32);
    const uint32_t s_wb1 = s_wb0 + WS_BYTES;

    {
        const __half* gx = g_xh + (size_t)p0 * XPAD_H;
        for (int i = tid; i < 128 * 10; i += MLP_THREADS) {
            int row = i / 10, ch = i - row * 10;
            cp16(s_act + (uint32_t)(row * (ACT_W * 2) + ch * 16),
                 gx + (size_t)row * XPAD_H + ch * 8);
        }
        const __half* gw = g_wpadh;
        for (int i = tid; i < WS_BYTES / 16; i += MLP_THREADS)
            cp16(s_wb0 + (uint32_t)i * 16, gw + i * 8);
    }
    CP_COMMIT();
    {
        const __half* gw = g_wpadh + (size_t)1 * 128 * WS_W;
        for (int i = tid; i < WS_BYTES / 16; i += MLP_THREADS)
            cp16(s_wb1 + (uint32_t)i * 16, gw + i * 8);
    }
    CP_COMMIT();

    if (tid < DH) {
        bias[0 * DH + tid] = b0[tid];
        bias[1 * DH + tid] = b1[tid];
        bias[2 * DH + tid] = b2[tid];
        bias[3 * DH + tid] = b3[tid];
        bias[4 * DH + tid] = b4[tid];
        dws[tid] = dw[tid];
    }
    for (int i = tid; i < DH * 3; i += MLP_THREADS) w5s[i] = w5[i];

    float acc[2][4][4];

#pragma unroll 1
    for (int l = 0; l < 5; l++) {
        if (l < 4) { CP_WAIT(1); } else { CP_WAIT(0); }
        __syncthreads();

        if (l == 1) {
            // sigma head from pf: 4 threads per point, half2 loads, shfl reduce
            int p = tid >> 2, quar = tid & 3;
            float sacc = 0.f;
            const __half2* arow =
                reinterpret_cast<const __half2*>(act_h + p * ACT_W + quar * 32);
#pragma unroll
            for (int j = 0; j < 16; j++) {
                float2 hv = __half22float2(arow[j]);
                int k = quar * 32 + j * 2;
                sacc = fmaf(hv.x, dws[k], sacc);
                sacc = fmaf(hv.y, dws[k + 1], sacc);
            }
            sacc += __shfl_xor_sync(0xffffffff, sacc, 1);
            sacc += __shfl_xor_sync(0xffffffff, sacc, 2);
            if (quar == 0)
                out[(size_t)(p0 + p) * 4 + 3] = fmaxf(sacc + db[0], 0.f);
        }

        const uint32_t* ws32 = wbuf32 + (l & 1) * (WS_BYTES / 4);
        if (l == 0) mma_gemm<5>(act32, ws32, acc, lane, m_blk, n_blk);
        else        mma_gemm<8>(act32, ws32, acc, lane, m_blk, n_blk);
        __syncthreads();

        if (l + 2 <= 4) {
            const __half* gw = g_wpadh + (size_t)(l + 2) * 128 * WS_W;
            uint32_t dst = (l & 1) ? s_wb1 : s_wb0;
            for (int i = tid; i < WS_BYTES / 16; i += MLP_THREADS)
                cp16(dst + (uint32_t)i * 16, gw + i * 8);
        }
        CP_COMMIT();

        epilogue(act32, bias + l * DH, acc, lane, m_blk, n_blk, l > 0);
    }
    __syncthreads();

    // rgb head: 4 threads per point, shfl reduce
    {
        int p = tid >> 2, quar = tid & 3;
        float r0 = 0.f, r1 = 0.f, r2 = 0.f;
        const __half2* arow =
            reinterpret_cast<const __half2*>(act_h + p * ACT_W + quar * 32);
#pragma unroll
        for (int j = 0; j < 16; j++) {
            float2 hv = __half22float2(arow[j]);
            int k = quar * 32 + j * 2;
            r0 = fmaf(hv.x, w5s[k * 3 + 0], r0);
            r1 = fmaf(hv.x, w5s[k * 3 + 1], r1);
            r2 = fmaf(hv.x, w5s[k * 3 + 2], r2);
            r0 = fmaf(hv.y, w5s[(k + 1) * 3 + 0], r0);
            r1 = fmaf(hv.y, w5s[(k + 1) * 3 + 1], r1);
            r2 = fmaf(hv.y, w5s[(k + 1) * 3 + 2], r2);
        }
        r0 += __shfl_xor_sync(0xffffffff, r0, 1);
        r0 += __shfl_xor_sync(0xffffffff, r0, 2);
        r1 += __shfl_xor_sync(0xffffffff, r1, 1);
        r1 += __shfl_xor_sync(0xffffffff, r1, 2);
        r2 += __shfl_xor_sync(0xffffffff, r2, 1);
        r2 += __shfl_xor_sync(0xffffffff, r2, 2);
        if (quar == 0) {
            size_t o = (size_t)(p0 + p) * 4;
            out[o + 0] = tanhf(r0 + b5[0]);
            out[o + 1] = tanhf(r1 + b5[1]);
            out[o + 2] = tanhf(r2 + b5[2]);
        }
    }
}

// ---------------------------------------------------------------------------
// Launch
// ---------------------------------------------------------------------------
extern "C" void kernel_launch(void* const* d_in, const int* in_sizes, int n_in,
                              void* d_out, int out_size) {
    const float* xyz       = (const float*)d_in[0];
    const float* src_imgs  = (const float*)d_in[2];
    const float* src_cams  = (const float*)d_in[3];
    const float* src_feats = (const float*)d_in[4];
    const float* w0 = (const float*)d_in[5];
    const float* b0 = (const float*)d_in[6];
    const float* w1 = (const float*)d_in[7];
    const float* b1 = (const float*)d_in[8];
    const float* w2 = (const float*)d_in[9];
    const float* b2 = (const float*)d_in[10];
    const float* w3 = (const float*)d_in[11];
    const float* b3 = (const float*)d_in[12];
    const float* w4 = (const float*)d_in[13];
    const float* b4 = (const float*)d_in[14];
    const float* w5 = (const float*)d_in[15];
    const float* b5 = (const float*)d_in[16];
    const float* dw = (const float*)d_in[17];
    const float* db = (const float*)d_in[18];
    float* out = (float*)d_out;

    const int smem_bytes = ACT_BYTES + 2 * WS_BYTES
                         + (5 * DH + DH * 3 + DH) * (int)sizeof(float);
    cudaFuncSetAttribute(mlp_mma_kernel,
                         cudaFuncAttributeMaxDynamicSharedMemorySize, smem_bytes);

    proj_kernel<<<1, 32>>>(src_cams);
    wprep_kernel<<<(5 * 128 * WS_W + 255) / 256, 256>>>(w0, w1, w2, w3, w4);
    tfeat_kernel<<<(B_ * NV * H1_ * W1_ * D_) / 256, 256>>>(src_feats);
    timg_kernel<<<(B_ * NV * H_ * W_ * 3 + 255) / 256, 256>>>(src_imgs);
    featurize_kernel<<<(PT * 4) / 256, 256>>>(xyz);
    mlp_mma_kernel<<<PT / TM, MLP_THREADS, smem_bytes>>>(b0, b1, b2, b3, b4,
                                                         w5, b5, dw, db, out);
}

// round 10
// speedup vs baseline: 1.1062x; 1.1062x over previous
#include <cuda_runtime.h>
#include <cuda_fp16.h>
#include <math.h>
#include <stdint.h>

// ---------------------------------------------------------------------------
// Problem constants
// ---------------------------------------------------------------------------
#define B_ 2
#define NV 4
#define H_ 240
#define W_ 240
#define H1_ 120
#define W1_ 120
#define D_ 32
#define NPB 131072
#define PT (B_ * NPB)
#define INBASE 70
#define XPAD_H 80             // padded fp16 feature row (160 B)
#define DH 128
#define TM 128
#define MLP_THREADS 512

#define ACT_W 136             // halves per act row (272 B, conflict-free)
#define ACT_W32 68
#define WS_W 136
#define WS_W32 68
#define ACT_BYTES (128 * ACT_W * 2)
#define WS_BYTES  (128 * WS_W * 2)

// ---------------------------------------------------------------------------
// Scratch (device globals)
// ---------------------------------------------------------------------------
__device__ __half g_xh[(size_t)PT * XPAD_H];
__device__ __half g_featsTh[(size_t)B_ * NV * H1_ * W1_ * D_]; // channel-last fp16 feats
__device__ __half g_imgsTh[(size_t)B_ * NV * H_ * W_ * 3];     // channel-last fp16 imgs
__device__ float  g_proj[B_ * NV * 12];
__device__ __half g_wpadh[5 * 128 * WS_W];

// ---------------------------------------------------------------------------
// helpers
// ---------------------------------------------------------------------------
__device__ __forceinline__ void mma_f16(float (&d)[4], const uint32_t (&a)[4],
                                        const uint32_t (&b)[2]) {
    asm volatile(
        "mma.sync.aligned.m16n8k16.row.col.f32.f16.f16.f32 "
        "{%0,%1,%2,%3}, {%4,%5,%6,%7}, {%8,%9}, {%0,%1,%2,%3};"
        : "+f"(d[0]), "+f"(d[1]), "+f"(d[2]), "+f"(d[3])
        : "r"(a[0]), "r"(a[1]), "r"(a[2]), "r"(a[3]), "r"(b[0]), "r"(b[1]));
}

__device__ __forceinline__ uint32_t smem_u32(const void* p) {
    return (uint32_t)__cvta_generic_to_shared(p);
}

__device__ __forceinline__ void cp16(uint32_t saddr, const void* g) {
    asm volatile("cp.async.cg.shared.global [%0], [%1], 16;" :: "r"(saddr), "l"(g));
}
#define CP_COMMIT() asm volatile("cp.async.commit_group;")
#define CP_WAIT(N)  asm volatile("cp.async.wait_group %0;" :: "n"(N))

// 8 halves (one uint4) -> 8 floats
__device__ __forceinline__ void h8_to_f(const uint4& u, float* f) {
    const __half2* h = reinterpret_cast<const __half2*>(&u);
#pragma unroll
    for (int i = 0; i < 4; i++) {
        float2 v = __half22float2(h[i]);
        f[i * 2 + 0] = v.x;
        f[i * 2 + 1] = v.y;
    }
}

// ---------------------------------------------------------------------------
// Kernel 0: projection matrices  P = K @ inv(c2w)[0:3, :]
// ---------------------------------------------------------------------------
__global__ void proj_kernel(const float* __restrict__ cams) {
    int i = threadIdx.x;
    if (i >= B_ * NV) return;
    const float* c = cams + i * 27;
    float K[9];
#pragma unroll
    for (int j = 0; j < 9; j++) K[j] = c[2 + j];
    float m[16];
#pragma unroll
    for (int j = 0; j < 16; j++) m[j] = c[11 + j];

    float inv[16];
    inv[0]  =  m[5]*m[10]*m[15] - m[5]*m[11]*m[14] - m[9]*m[6]*m[15] + m[9]*m[7]*m[14] + m[13]*m[6]*m[11] - m[13]*m[7]*m[10];
    inv[4]  = -m[4]*m[10]*m[15] + m[4]*m[11]*m[14] + m[8]*m[6]*m[15] - m[8]*m[7]*m[14] - m[12]*m[6]*m[11] + m[12]*m[7]*m[10];
    inv[8]  =  m[4]*m[9]*m[15]  - m[4]*m[11]*m[13] - m[8]*m[5]*m[15] + m[8]*m[7]*m[13] + m[12]*m[5]*m[11] - m[12]*m[7]*m[9];
    inv[12] = -m[4]*m[9]*m[14]  + m[4]*m[10]*m[13] + m[8]*m[5]*m[14] - m[8]*m[6]*m[13] - m[12]*m[5]*m[10] + m[12]*m[6]*m[9];
    inv[1]  = -m[1]*m[10]*m[15] + m[1]*m[11]*m[14] + m[9]*m[2]*m[15] - m[9]*m[3]*m[14] - m[13]*m[2]*m[11] + m[13]*m[3]*m[10];
    inv[5]  =  m[0]*m[10]*m[15] - m[0]*m[11]*m[14] - m[8]*m[2]*m[15] + m[8]*m[3]*m[14] + m[12]*m[2]*m[11] - m[12]*m[3]*m[10];
    inv[9]  = -m[0]*m[9]*m[15]  + m[0]*m[11]*m[13] + m[8]*m[1]*m[15] - m[8]*m[3]*m[13] - m[12]*m[1]*m[11] + m[12]*m[3]*m[9];
    inv[13] =  m[0]*m[9]*m[14]  - m[0]*m[10]*m[13] - m[8]*m[1]*m[14] + m[8]*m[2]*m[13] + m[12]*m[1]*m[10] - m[12]*m[2]*m[9];
    inv[2]  =  m[1]*m[6]*m[15]  - m[1]*m[7]*m[14]  - m[5]*m[2]*m[15] + m[5]*m[3]*m[14] + m[13]*m[2]*m[7]  - m[13]*m[3]*m[6];
    inv[6]  = -m[0]*m[6]*m[15]  + m[0]*m[7]*m[14]  + m[4]*m[2]*m[15] - m[4]*m[3]*m[14] - m[12]*m[2]*m[7]  + m[12]*m[3]*m[6];
    inv[10] =  m[0]*m[5]*m[15]  - m[0]*m[7]*m[13]  - m[4]*m[1]*m[15] + m[4]*m[3]*m[13] + m[12]*m[1]*m[7]  - m[12]*m[3]*m[5];
    inv[14] = -m[0]*m[5]*m[14]  + m[0]*m[6]*m[13]  + m[4]*m[1]*m[14] - m[4]*m[2]*m[13] - m[12]*m[1]*m[6]  + m[12]*m[2]*m[5];
    inv[3]  = -m[1]*m[6]*m[11]  + m[1]*m[7]*m[10]  + m[5]*m[2]*m[11] - m[5]*m[3]*m[10] - m[9]*m[2]*m[7]   + m[9]*m[3]*m[6];
    inv[7]  =  m[0]*m[6]*m[11]  - m[0]*m[7]*m[10]  - m[4]*m[2]*m[11] + m[4]*m[3]*m[10] + m[8]*m[2]*m[7]   - m[8]*m[3]*m[6];
    inv[11] = -m[0]*m[5]*m[11]  + m[0]*m[7]*m[9]   + m[4]*m[1]*m[11] - m[4]*m[3]*m[9]  - m[8]*m[1]*m[7]   + m[8]*m[3]*m[5];
    inv[15] =  m[0]*m[5]*m[10]  - m[0]*m[6]*m[9]   - m[4]*m[1]*m[10] + m[4]*m[2]*m[9]  + m[8]*m[1]*m[6]   - m[8]*m[2]*m[5];

    float det = m[0]*inv[0] + m[1]*inv[4] + m[2]*inv[8] + m[3]*inv[12];
    float id = 1.0f / det;
#pragma unroll
    for (int j = 0; j < 16; j++) inv[j] *= id;

#pragma unroll
    for (int r = 0; r < 3; r++) {
#pragma unroll
        for (int cc = 0; cc < 4; cc++) {
            float s = K[r*3+0]*inv[0*4+cc] + K[r*3+1]*inv[1*4+cc] + K[r*3+2]*inv[2*4+cc];
            g_proj[i*12 + r*4 + cc] = s;
        }
    }
}

// ---------------------------------------------------------------------------
// Weight prep: fp16, transposed [l][n][k]
// ---------------------------------------------------------------------------
__global__ void wprep_kernel(const float* __restrict__ w0, const float* __restrict__ w1,
                             const float* __restrict__ w2, const float* __restrict__ w3,
                             const float* __restrict__ w4) {
    int o = blockIdx.x * blockDim.x + threadIdx.x;
    if (o >= 5 * 128 * WS_W) return;
    int l = o / (128 * WS_W);
    int rem = o - l * 128 * WS_W;
    int n = rem / WS_W;
    int k = rem - n * WS_W;
    float v = 0.f;
    if (l == 0) {
        if (k < INBASE) v = w0[k * DH + n];
    } else if (k < DH) {
        const float* w = (l == 1) ? w1 : (l == 2) ? w2 : (l == 3) ? w3 : w4;
        v = w[k * DH + n];
    }
    g_wpadh[o] = __float2half_rn(v);
}

// ---------------------------------------------------------------------------
// Transposes to channel-last fp16
// ---------------------------------------------------------------------------
__global__ void tfeat_kernel(const float* __restrict__ f) {
    int o = blockIdx.x * blockDim.x + threadIdx.x;
    if (o >= B_ * NV * H1_ * W1_ * D_) return;
    int c = o & (D_ - 1);
    int rest = o >> 5;
    int x = rest % W1_;
    int t2 = rest / W1_;
    int y = t2 % H1_;
    int bv = t2 / H1_;
    g_featsTh[o] = __float2half_rn(f[((size_t)(bv * D_ + c)) * (H1_ * W1_) + y * W1_ + x]);
}

__global__ void timg_kernel(const float* __restrict__ im) {
    int o = blockIdx.x * blockDim.x + threadIdx.x;
    if (o >= B_ * NV * H_ * W_ * 3) return;
    int c = o % 3;
    int rest = o / 3;
    int x = rest % W_;
    int t2 = rest / W_;
    int y = t2 % H_;
    int bv = t2 / H_;
    g_imgsTh[o] = __float2half_rn(im[((size_t)(bv * 3 + c)) * (H_ * W_) + y * W_ + x]);
}

// ---------------------------------------------------------------------------
// Kernel 1: quad featurize (4 threads/point), fp16 taps -> g_xh [PT][80]
// ---------------------------------------------------------------------------
__global__ void __launch_bounds__(256) featurize_kernel(const float* __restrict__ xyz) {
    int t = blockIdx.x * blockDim.x + threadIdx.x;
    int gp = t >> 2;
    int q  = t & 3;
    if (gp >= PT) return;
    int b = gp / NPB;

    float X = xyz[(size_t)gp * 3 + 0];
    float Y = xyz[(size_t)gp * 3 + 1];
    float Z = xyz[(size_t)gp * 3 + 2];

    float fs[8], fq[8];
#pragma unroll
    for (int i = 0; i < 8; i++) { fs[i] = 0.f; fq[i] = 0.f; }
    float rs = 0.f, rq = 0.f;
    float s = 0.f;

    const float SX = (float)(W1_ - 1) / (float)(W_ - 1);
    const float SY = (float)(H1_ - 1) / (float)(H_ - 1);

#pragma unroll
    for (int v = 0; v < NV; v++) {
        const float* Pm = &g_proj[(b * NV + v) * 12];
        float pxn = Pm[0]*X + Pm[1]*Y + Pm[2]*Z  + Pm[3];
        float pyn = Pm[4]*X + Pm[5]*Y + Pm[6]*Z  + Pm[7];
        float pz  = Pm[8]*X + Pm[9]*Y + Pm[10]*Z + Pm[11];
        float d = fmaxf(pz, 1e-8f);
        float px = pxn / d;
        float py = pyn / d;
        bool inb = (pz > 1e-4f) && (px >= 0.f) && (px <= (float)(W_ - 1))
                                && (py >= 0.f) && (py <= (float)(H_ - 1));
        if (!inb) continue;
        s += 1.f;

        if (q < 3) {
            float x0f = floorf(px), y0f = floorf(py);
            float wx = px - x0f, wy = py - y0f;
            int x0 = (int)x0f;
            int y0 = (int)y0f;
            int x1 = min(x0 + 1, W_ - 1);
            int y1 = min(y0 + 1, H_ - 1);
            float w00 = (1.f - wx) * (1.f - wy);
            float w01 = wx * (1.f - wy);
            float w10 = (1.f - wx) * wy;
            float w11 = wx * wy;
            const __half* ib = g_imgsTh + (size_t)(b * NV + v) * H_ * W_ * 3 + q;
            float val = __half2float(ib[(size_t)(y0 * W_ + x0) * 3]) * w00
                      + __half2float(ib[(size_t)(y0 * W_ + x1) * 3]) * w01
                      + __half2float(ib[(size_t)(y1 * W_ + x0) * 3]) * w10
                      + __half2float(ib[(size_t)(y1 * W_ + x1) * 3]) * w11;
            rs += val;
            rq += val * val;
        }

        {
            float fx = px * SX;
            float fy = py * SY;
            float x0f = floorf(fx), y0f = floorf(fy);
            float wx = fx - x0f, wy = fy - y0f;
            int x0 = (int)x0f;
            int y0 = (int)y0f;
            int x1 = min(x0 + 1, W1_ - 1);
            int y1 = min(y0 + 1, H1_ - 1);
            float w00 = (1.f - wx) * (1.f - wy);
            float w01 = wx * (1.f - wy);
            float w10 = (1.f - wx) * wy;
            float w11 = wx * wy;
            const __half* fb = g_featsTh + (size_t)(b * NV + v) * H1_ * W1_ * D_ + q * 8;
            uint4 u00 = *reinterpret_cast<const uint4*>(fb + (size_t)(y0 * W1_ + x0) * D_);
            uint4 u01 = *reinterpret_cast<const uint4*>(fb + (size_t)(y0 * W1_ + x1) * D_);
            uint4 u10 = *reinterpret_cast<const uint4*>(fb + (size_t)(y1 * W1_ + x0) * D_);
            uint4 u11 = *reinterpret_cast<const uint4*>(fb + (size_t)(y1 * W1_ + x1) * D_);
            float a[8], bb[8], cc[8], dd[8];
            h8_to_f(u00, a); h8_to_f(u01, bb); h8_to_f(u10, cc); h8_to_f(u11, dd);
#pragma unroll
            for (int j = 0; j < 8; j++) {
                float vv = a[j]*w00 + bb[j]*w01 + cc[j]*w10 + dd[j]*w11;
                fs[j] += vv;
                fq[j] += vv * vv;
            }
        }
    }

    float denom = s + 1e-6f;
    float invd = 1.f / denom;
    float alpha = s * invd;
    float two_m_a = 2.f - alpha;
    __half* xo = g_xh + (size_t)gp * XPAD_H;

    if (q < 3) {
        float m  = rs * invd;
        float e2 = rq * invd;
        xo[q]      = __float2half_rn(m);
        xo[35 + q] = __float2half_rn(e2 - two_m_a * m * m);
    }
#pragma unroll
    for (int j = 0; j < 8; j++) {
        int i = 3 + q * 8 + j;
        float m  = fs[j] * invd;
        float e2 = fq[j] * invd;
        xo[i]      = __float2half_rn(m);
        xo[35 + i] = __float2half_rn(e2 - two_m_a * m * m);
    }
    if (q == 0) {
#pragma unroll
        for (int j = 70; j < XPAD_H; j++) xo[j] = __float2half_rn(0.f);
    }
}

// ---------------------------------------------------------------------------
// Kernel 2: fused MLP, fp16 mma.m16n8k16, 512 threads, 2 blocks/SM
// (heads in round-8 form: tid<TM serial, overlapped with other warps' MMA)
// ---------------------------------------------------------------------------
template <int KSTEPS>
__device__ __forceinline__ void mma_gemm(const uint32_t* __restrict__ act32,
                                         const uint32_t* __restrict__ ws32,
                                         float (&acc)[2][4][4],
                                         int lane, int m_blk, int n_blk) {
#pragma unroll
    for (int mi = 0; mi < 2; mi++)
#pragma unroll
        for (int ni = 0; ni < 4; ni++)
#pragma unroll
            for (int j = 0; j < 4; j++) acc[mi][ni][j] = 0.f;

    const int r = lane >> 2;
    const int cp = lane & 3;

#pragma unroll
    for (int kt = 0; kt < KSTEPS; kt++) {
        const int k32 = kt * 8;
        uint32_t a[2][4];
#pragma unroll
        for (int mi = 0; mi < 2; mi++) {
            const int base = (m_blk * 32 + mi * 16 + r) * ACT_W32 + k32 + cp;
            a[mi][0] = act32[base];
            a[mi][1] = act32[base + 8 * ACT_W32];
            a[mi][2] = act32[base + 4];
            a[mi][3] = act32[base + 8 * ACT_W32 + 4];
        }
        uint32_t bf[4][2];
#pragma unroll
        for (int ni = 0; ni < 4; ni++) {
            const int n = n_blk * 32 + ni * 8 + r;
            const int bbase = n * WS_W32 + k32 + cp;
            bf[ni][0] = ws32[bbase];
            bf[ni][1] = ws32[bbase + 4];
        }
#pragma unroll
        for (int mi = 0; mi < 2; mi++)
#pragma unroll
            for (int ni = 0; ni < 4; ni++)
                mma_f16(acc[mi][ni], a[mi], bf[ni]);
    }
}

__device__ __forceinline__ void epilogue(uint32_t* __restrict__ act32,
                                         const float* __restrict__ bs,
                                         float (&acc)[2][4][4],
                                         int lane, int m_blk, int n_blk,
                                         bool leaky) {
    const int r = lane >> 2;
    const int cp = lane & 3;
#pragma unroll
    for (int mi = 0; mi < 2; mi++) {
        const int row0 = m_blk * 32 + mi * 16 + r;
#pragma unroll
        for (int ni = 0; ni < 4; ni++) {
            const int col = n_blk * 32 + ni * 8 + cp * 2;
            float v0 = acc[mi][ni][0] + bs[col];
            float v1 = acc[mi][ni][1] + bs[col + 1];
            float v2 = acc[mi][ni][2] + bs[col];
            float v3 = acc[mi][ni][3] + bs[col + 1];
            if (leaky) {
                v0 = v0 > 0.f ? v0 : 0.01f * v0;
                v1 = v1 > 0.f ? v1 : 0.01f * v1;
                v2 = v2 > 0.f ? v2 : 0.01f * v2;
                v3 = v3 > 0.f ? v3 : 0.01f * v3;
            }
            __half2 h01 = __halves2half2(__float2half_rn(v0), __float2half_rn(v1));
            __half2 h23 = __halves2half2(__float2half_rn(v2), __float2half_rn(v3));
            act32[row0 * ACT_W32 + col / 2]       = *reinterpret_cast<uint32_t*>(&h01);
            act32[(row0 + 8) * ACT_W32 + col / 2] = *reinterpret_cast<uint32_t*>(&h23);
        }
    }
}

__global__ void __launch_bounds__(MLP_THREADS, 2) mlp_mma_kernel(
    const float* __restrict__ b0, const float* __restrict__ b1,
    const float* __restrict__ b2, const float* __restrict__ b3,
    const float* __restrict__ b4,
    const float* __restrict__ w5, const float* __restrict__ b5,
    const float* __restrict__ dw, const float* __restrict__ db,
    float* __restrict__ out) {

    extern __shared__ char smem[];
    uint32_t* act32 = reinterpret_cast<uint32_t*>(smem);
    uint32_t* wbuf32 = reinterpret_cast<uint32_t*>(smem + ACT_BYTES);
    float* bias = reinterpret_cast<float*>(smem + ACT_BYTES + 2 * WS_BYTES);
    float* w5s  = bias + 5 * DH;
    float* dws  = w5s + DH * 3;
    const __half* act_h = reinterpret_cast<const __half*>(smem);

    const int tid  = threadIdx.x;
    const int lane = tid & 31;
    const int warp = tid >> 5;
    const int m_blk = warp & 3;
    const int n_blk = warp >> 2;
    const int p0 = blockIdx.x * TM;

    const uint32_t s_act = smem_u32(act32);
    const uint32_t s_wb0 = smem_u32(wbuf32);
    const uint32_t s_wb1 = s_wb0 + WS_BYTES;

    {
        const __half* gx = g_xh + (size_t)p0 * XPAD_H;
        for (int i = tid; i < 128 * 10; i += MLP_THREADS) {
            int row = i / 10, ch = i - row * 10;
            cp16(s_act + (uint32_t)(row * (ACT_W * 2) + ch * 16),
                 gx + (size_t)row * XPAD_H + ch * 8);
        }
        const __half* gw = g_wpadh;
        for (int i = tid; i < WS_BYTES / 16; i += MLP_THREADS)
            cp16(s_wb0 + (uint32_t)i * 16, gw + i * 8);
    }
    CP_COMMIT();
    {
        const __half* gw = g_wpadh + (size_t)1 * 128 * WS_W;
        for (int i = tid; i < WS_BYTES / 16; i += MLP_THREADS)
            cp16(s_wb1 + (uint32_t)i * 16, gw + i * 8);
    }
    CP_COMMIT();

    if (tid < DH) {
        bias[0 * DH + tid] = b0[tid];
        bias[1 * DH + tid] = b1[tid];
        bias[2 * DH + tid] = b2[tid];
        bias[3 * DH + tid] = b3[tid];
        bias[4 * DH + tid] = b4[tid];
        dws[tid] = dw[tid];
    }
    for (int i = tid; i < DH * 3; i += MLP_THREADS) w5s[i] = w5[i];

    float acc[2][4][4];

#pragma unroll 1
    for (int l = 0; l < 5; l++) {
        if (l < 4) { CP_WAIT(1); } else { CP_WAIT(0); }
        __syncthreads();

        if (l == 1 && tid < TM) {
            // sigma head from pf (only warps 0-3; others proceed to MMA -> overlap)
            float sacc = db[0];
#pragma unroll 4
            for (int kk = 0; kk < DH; kk++) {
                int k = (kk + lane) & (DH - 1);
                sacc = fmaf(__half2float(act_h[tid * ACT_W + k]), dws[k], sacc);
            }
            out[(size_t)(p0 + tid) * 4 + 3] = fmaxf(sacc, 0.f);
        }

        const uint32_t* ws32 = wbuf32 + (l & 1) * (WS_BYTES / 4);
        if (l == 0) mma_gemm<5>(act32, ws32, acc, lane, m_blk, n_blk);
        else        mma_gemm<8>(act32, ws32, acc, lane, m_blk, n_blk);
        __syncthreads();

        if (l + 2 <= 4) {
            const __half* gw = g_wpadh + (size_t)(l + 2) * 128 * WS_W;
            uint32_t dst = (l & 1) ? s_wb1 : s_wb0;
            for (int i = tid; i < WS_BYTES / 16; i += MLP_THREADS)
                cp16(dst + (uint32_t)i * 16, gw + i * 8);
        }
        CP_COMMIT();

        epilogue(act32, bias + l * DH, acc, lane, m_blk, n_blk, l > 0);
    }
    __syncthreads();

    // rgb head (round-8 form)
    if (tid < TM) {
        float r0 = b5[0], r1 = b5[1], r2 = b5[2];
#pragma unroll 4
        for (int kk = 0; kk < DH; kk++) {
            int k = (kk + lane) & (DH - 1);
            float hv = __half2float(act_h[tid * ACT_W + k]);
            r0 = fmaf(hv, w5s[k * 3 + 0], r0);
            r1 = fmaf(hv, w5s[k * 3 + 1], r1);
            r2 = fmaf(hv, w5s[k * 3 + 2], r2);
        }
        size_t o = (size_t)(p0 + tid) * 4;
        out[o + 0] = tanhf(r0);
        out[o + 1] = tanhf(r1);
        out[o + 2] = tanhf(r2);
    }
}

// ---------------------------------------------------------------------------
// Launch
// ---------------------------------------------------------------------------
extern "C" void kernel_launch(void* const* d_in, const int* in_sizes, int n_in,
                              void* d_out, int out_size) {
    const float* xyz       = (const float*)d_in[0];
    const float* src_imgs  = (const float*)d_in[2];
    const float* src_cams  = (const float*)d_in[3];
    const float* src_feats = (const float*)d_in[4];
    const float* w0 = (const float*)d_in[5];
    const float* b0 = (const float*)d_in[6];
    const float* w1 = (const float*)d_in[7];
    const float* b1 = (const float*)d_in[8];
    const float* w2 = (const float*)d_in[9];
    const float* b2 = (const float*)d_in[10];
    const float* w3 = (const float*)d_in[11];
    const float* b3 = (const float*)d_in[12];
    const float* w4 = (const float*)d_in[13];
    const float* b4 = (const float*)d_in[14];
    const float* w5 = (const float*)d_in[15];
    const float* b5 = (const float*)d_in[16];
    const float* dw = (const float*)d_in[17];
    const float* db = (const float*)d_in[18];
    float* out = (float*)d_out;

    const int smem_bytes = ACT_BYTES + 2 * WS_BYTES
                         + (5 * DH + DH * 3 + DH) * (int)sizeof(float);
    cudaFuncSetAttribute(mlp_mma_kernel,
                         cudaFuncAttributeMaxDynamicSharedMemorySize, smem_bytes);

    proj_kernel<<<1, 32>>>(src_cams);
    wprep_kernel<<<(5 * 128 * WS_W + 255) / 256, 256>>>(w0, w1, w2, w3, w4);
    tfeat_kernel<<<(B_ * NV * H1_ * W1_ * D_) / 256, 256>>>(src_feats);
    timg_kernel<<<(B_ * NV * H_ * W_ * 3 + 255) / 256, 256>>>(src_imgs);
    featurize_kernel<<<(PT * 4) / 256, 256>>>(xyz);
    mlp_mma_kernel<<<PT / TM, MLP_THREADS, smem_bytes>>>(b0, b1, b2, b3, b4,
                                                         w5, b5, dw, db, out);
}

// round 11
// speedup vs baseline: 1.2873x; 1.1637x over previous
#include <cuda_runtime.h>
#include <cuda_fp16.h>
#include <math.h>
#include <stdint.h>

// ---------------------------------------------------------------------------
// Problem constants
// ---------------------------------------------------------------------------
#define B_ 2
#define NV 4
#define H_ 240
#define W_ 240
#define H1_ 120
#define W1_ 120
#define D_ 32
#define NPB 131072
#define PT (B_ * NPB)
#define INBASE 70
#define XPAD_H 80             // padded fp16 feature row (160 B)
#define DH 128
#define TM 128                // points per tile
#define NT (PT / TM)          // 2048 tiles
#define FF_GRID 148           // persistent blocks (1/SM on B200)
#define FF_THREADS 256        // 8 warps x 16 rows = 128 = TM

#define WS_W 136              // halves per weight row [n][k] (272 B, conflict-free)
#define WS_W32 68
#define WL_W32 (128 * WS_W32)         // words per layer = 8704
#define WS_ALL_BYTES (5 * 128 * WS_W * 2)  // 174080

#define ACTIN_W32 84          // words per act-in row (336 B; (20r+c) banks conflict-free)
#define ACTIN_BYTES (128 * ACTIN_W32 * 4)  // 43008

// ---------------------------------------------------------------------------
// Scratch (device globals)
// ---------------------------------------------------------------------------
__device__ __half g_xh[(size_t)PT * XPAD_H];
__device__ __half g_featsTh[(size_t)B_ * NV * H1_ * W1_ * D_];
__device__ __half g_imgsTh[(size_t)B_ * NV * H_ * W_ * 3];
__device__ float  g_proj[B_ * NV * 12];
__device__ __half g_wpadh[5 * 128 * WS_W];   // [l][n][k] fp16, k-padded

// ---------------------------------------------------------------------------
// helpers
// ---------------------------------------------------------------------------
__device__ __forceinline__ void mma_f16(float (&d)[4], const uint32_t (&a)[4],
                                        const uint32_t (&b)[2]) {
    asm volatile(
        "mma.sync.aligned.m16n8k16.row.col.f32.f16.f16.f32 "
        "{%0,%1,%2,%3}, {%4,%5,%6,%7}, {%8,%9}, {%0,%1,%2,%3};"
        : "+f"(d[0]), "+f"(d[1]), "+f"(d[2]), "+f"(d[3])
        : "r"(a[0]), "r"(a[1]), "r"(a[2]), "r"(a[3]), "r"(b[0]), "r"(b[1]));
}

__device__ __forceinline__ uint32_t smem_u32(const void* p) {
    return (uint32_t)__cvta_generic_to_shared(p);
}

__device__ __forceinline__ void cp16(uint32_t saddr, const void* g) {
    asm volatile("cp.async.cg.shared.global [%0], [%1], 16;" :: "r"(saddr), "l"(g));
}
#define CP_COMMIT() asm volatile("cp.async.commit_group;")
#define CP_WAIT0()  asm volatile("cp.async.wait_group 0;")

__device__ __forceinline__ uint32_t pack_h2(float x, float y) {
    __half2 h = __halves2half2(__float2half_rn(x), __float2half_rn(y));
    return *reinterpret_cast<uint32_t*>(&h);
}

__device__ __forceinline__ void h8_to_f(const uint4& u, float* f) {
    const __half2* h = reinterpret_cast<const __half2*>(&u);
#pragma unroll
    for (int i = 0; i < 4; i++) {
        float2 v = __half22float2(h[i]);
        f[i * 2 + 0] = v.x;
        f[i * 2 + 1] = v.y;
    }
}

// ---------------------------------------------------------------------------
// Kernel 0: projection matrices  P = K @ inv(c2w)[0:3, :]
// ---------------------------------------------------------------------------
__global__ void proj_kernel(const float* __restrict__ cams) {
    int i = threadIdx.x;
    if (i >= B_ * NV) return;
    const float* c = cams + i * 27;
    float K[9];
#pragma unroll
    for (int j = 0; j < 9; j++) K[j] = c[2 + j];
    float m[16];
#pragma unroll
    for (int j = 0; j < 16; j++) m[j] = c[11 + j];

    float inv[16];
    inv[0]  =  m[5]*m[10]*m[15] - m[5]*m[11]*m[14] - m[9]*m[6]*m[15] + m[9]*m[7]*m[14] + m[13]*m[6]*m[11] - m[13]*m[7]*m[10];
    inv[4]  = -m[4]*m[10]*m[15] + m[4]*m[11]*m[14] + m[8]*m[6]*m[15] - m[8]*m[7]*m[14] - m[12]*m[6]*m[11] + m[12]*m[7]*m[10];
    inv[8]  =  m[4]*m[9]*m[15]  - m[4]*m[11]*m[13] - m[8]*m[5]*m[15] + m[8]*m[7]*m[13] + m[12]*m[5]*m[11] - m[12]*m[7]*m[9];
    inv[12] = -m[4]*m[9]*m[14]  + m[4]*m[10]*m[13] + m[8]*m[5]*m[14] - m[8]*m[6]*m[13] - m[12]*m[5]*m[10] + m[12]*m[6]*m[9];
    inv[1]  = -m[1]*m[10]*m[15] + m[1]*m[11]*m[14] + m[9]*m[2]*m[15] - m[9]*m[3]*m[14] - m[13]*m[2]*m[11] + m[13]*m[3]*m[10];
    inv[5]  =  m[0]*m[10]*m[15] - m[0]*m[11]*m[14] - m[8]*m[2]*m[15] + m[8]*m[3]*m[14] + m[12]*m[2]*m[11] - m[12]*m[3]*m[10];
    inv[9]  = -m[0]*m[9]*m[15]  + m[0]*m[11]*m[13] + m[8]*m[1]*m[15] - m[8]*m[3]*m[13] - m[12]*m[1]*m[11] + m[12]*m[3]*m[9];
    inv[13] =  m[0]*m[9]*m[14]  - m[0]*m[10]*m[13] - m[8]*m[1]*m[14] + m[8]*m[2]*m[13] + m[12]*m[1]*m[10] - m[12]*m[2]*m[9];
    inv[2]  =  m[1]*m[6]*m[15]  - m[1]*m[7]*m[14]  - m[5]*m[2]*m[15] + m[5]*m[3]*m[14] + m[13]*m[2]*m[7]  - m[13]*m[3]*m[6];
    inv[6]  = -m[0]*m[6]*m[15]  + m[0]*m[7]*m[14]  + m[4]*m[2]*m[15] - m[4]*m[3]*m[14] - m[12]*m[2]*m[7]  + m[12]*m[3]*m[6];
    inv[10] =  m[0]*m[5]*m[15]  - m[0]*m[7]*m[13]  - m[4]*m[1]*m[15] + m[4]*m[3]*m[13] + m[12]*m[1]*m[7]  - m[12]*m[3]*m[5];
    inv[14] = -m[0]*m[5]*m[14]  + m[0]*m[6]*m[13]  + m[4]*m[1]*m[14] - m[4]*m[2]*m[13] - m[12]*m[1]*m[6]  + m[12]*m[2]*m[5];
    inv[3]  = -m[1]*m[6]*m[11]  + m[1]*m[7]*m[10]  + m[5]*m[2]*m[11] - m[5]*m[3]*m[10] - m[9]*m[2]*m[7]   + m[9]*m[3]*m[6];
    inv[7]  =  m[0]*m[6]*m[11]  - m[0]*m[7]*m[10]  - m[4]*m[2]*m[11] + m[4]*m[3]*m[10] + m[8]*m[2]*m[7]   - m[8]*m[3]*m[6];
    inv[11] = -m[0]*m[5]*m[11]  + m[0]*m[7]*m[9]   + m[4]*m[1]*m[11] - m[4]*m[3]*m[9]  - m[8]*m[1]*m[7]   + m[8]*m[3]*m[5];
    inv[15] =  m[0]*m[5]*m[10]  - m[0]*m[6]*m[9]   - m[4]*m[1]*m[10] + m[4]*m[2]*m[9]  + m[8]*m[1]*m[6]   - m[8]*m[2]*m[5];

    float det = m[0]*inv[0] + m[1]*inv[4] + m[2]*inv[8] + m[3]*inv[12];
    float id = 1.0f / det;
#pragma unroll
    for (int j = 0; j < 16; j++) inv[j] *= id;

#pragma unroll
    for (int r = 0; r < 3; r++) {
#pragma unroll
        for (int cc = 0; cc < 4; cc++) {
            float s = K[r*3+0]*inv[0*4+cc] + K[r*3+1]*inv[1*4+cc] + K[r*3+2]*inv[2*4+cc];
            g_proj[i*12 + r*4 + cc] = s;
        }
    }
}

// ---------------------------------------------------------------------------
// Weight prep: fp16, transposed [l][n][k]
// ---------------------------------------------------------------------------
__global__ void wprep_kernel(const float* __restrict__ w0, const float* __restrict__ w1,
                             const float* __restrict__ w2, const float* __restrict__ w3,
                             const float* __restrict__ w4) {
    int o = blockIdx.x * blockDim.x + threadIdx.x;
    if (o >= 5 * 128 * WS_W) return;
    int l = o / (128 * WS_W);
    int rem = o - l * 128 * WS_W;
    int n = rem / WS_W;
    int k = rem - n * WS_W;
    float v = 0.f;
    if (l == 0) {
        if (k < INBASE) v = w0[k * DH + n];
    } else if (k < DH) {
        const float* w = (l == 1) ? w1 : (l == 2) ? w2 : (l == 3) ? w3 : w4;
        v = w[k * DH + n];
    }
    g_wpadh[o] = __float2half_rn(v);
}

// ---------------------------------------------------------------------------
// Transposes to channel-last fp16
// ---------------------------------------------------------------------------
__global__ void tfeat_kernel(const float* __restrict__ f) {
    int o = blockIdx.x * blockDim.x + threadIdx.x;
    if (o >= B_ * NV * H1_ * W1_ * D_) return;
    int c = o & (D_ - 1);
    int rest = o >> 5;
    int x = rest % W1_;
    int t2 = rest / W1_;
    int y = t2 % H1_;
    int bv = t2 / H1_;
    g_featsTh[o] = __float2half_rn(f[((size_t)(bv * D_ + c)) * (H1_ * W1_) + y * W1_ + x]);
}

__global__ void timg_kernel(const float* __restrict__ im) {
    int o = blockIdx.x * blockDim.x + threadIdx.x;
    if (o >= B_ * NV * H_ * W_ * 3) return;
    int c = o % 3;
    int rest = o / 3;
    int x = rest % W_;
    int t2 = rest / W_;
    int y = t2 % H_;
    int bv = t2 / H_;
    g_imgsTh[o] = __float2half_rn(im[((size_t)(bv * 3 + c)) * (H_ * W_) + y * W_ + x]);
}

// ---------------------------------------------------------------------------
// Kernel 1: quad featurize (4 threads/point), fp16 taps -> g_xh [PT][80]
// ---------------------------------------------------------------------------
__global__ void __launch_bounds__(256) featurize_kernel(const float* __restrict__ xyz) {
    int t = blockIdx.x * blockDim.x + threadIdx.x;
    int gp = t >> 2;
    int q  = t & 3;
    if (gp >= PT) return;
    int b = gp / NPB;

    float X = xyz[(size_t)gp * 3 + 0];
    float Y = xyz[(size_t)gp * 3 + 1];
    float Z = xyz[(size_t)gp * 3 + 2];

    float fs[8], fq[8];
#pragma unroll
    for (int i = 0; i < 8; i++) { fs[i] = 0.f; fq[i] = 0.f; }
    float rs = 0.f, rq = 0.f;
    float s = 0.f;

    const float SX = (float)(W1_ - 1) / (float)(W_ - 1);
    const float SY = (float)(H1_ - 1) / (float)(H_ - 1);

#pragma unroll
    for (int v = 0; v < NV; v++) {
        const float* Pm = &g_proj[(b * NV + v) * 12];
        float pxn = Pm[0]*X + Pm[1]*Y + Pm[2]*Z  + Pm[3];
        float pyn = Pm[4]*X + Pm[5]*Y + Pm[6]*Z  + Pm[7];
        float pz  = Pm[8]*X + Pm[9]*Y + Pm[10]*Z + Pm[11];
        float d = fmaxf(pz, 1e-8f);
        float px = pxn / d;
        float py = pyn / d;
        bool inb = (pz > 1e-4f) && (px >= 0.f) && (px <= (float)(W_ - 1))
                                && (py >= 0.f) && (py <= (float)(H_ - 1));
        if (!inb) continue;
        s += 1.f;

        if (q < 3) {
            float x0f = floorf(px), y0f = floorf(py);
            float wx = px - x0f, wy = py - y0f;
            int x0 = (int)x0f;
            int y0 = (int)y0f;
            int x1 = min(x0 + 1, W_ - 1);
            int y1 = min(y0 + 1, H_ - 1);
            float w00 = (1.f - wx) * (1.f - wy);
            float w01 = wx * (1.f - wy);
            float w10 = (1.f - wx) * wy;
            float w11 = wx * wy;
            const __half* ib = g_imgsTh + (size_t)(b * NV + v) * H_ * W_ * 3 + q;
            float val = __half2float(ib[(size_t)(y0 * W_ + x0) * 3]) * w00
                      + __half2float(ib[(size_t)(y0 * W_ + x1) * 3]) * w01
                      + __half2float(ib[(size_t)(y1 * W_ + x0) * 3]) * w10
                      + __half2float(ib[(size_t)(y1 * W_ + x1) * 3]) * w11;
            rs += val;
            rq += val * val;
        }

        {
            float fx = px * SX;
            float fy = py * SY;
            float x0f = floorf(fx), y0f = floorf(fy);
            float wx = fx - x0f, wy = fy - y0f;
            int x0 = (int)x0f;
            int y0 = (int)y0f;
            int x1 = min(x0 + 1, W1_ - 1);
            int y1 = min(y0 + 1, H1_ - 1);
            float w00 = (1.f - wx) * (1.f - wy);
            float w01 = wx * (1.f - wy);
            float w10 = (1.f - wx) * wy;
            float w11 = wx * wy;
            const __half* fb = g_featsTh + (size_t)(b * NV + v) * H1_ * W1_ * D_ + q * 8;
            uint4 u00 = *reinterpret_cast<const uint4*>(fb + (size_t)(y0 * W1_ + x0) * D_);
            uint4 u01 = *reinterpret_cast<const uint4*>(fb + (size_t)(y0 * W1_ + x1) * D_);
            uint4 u10 = *reinterpret_cast<const uint4*>(fb + (size_t)(y1 * W1_ + x0) * D_);
            uint4 u11 = *reinterpret_cast<const uint4*>(fb + (size_t)(y1 * W1_ + x1) * D_);
            float a[8], bb[8], cc[8], dd[8];
            h8_to_f(u00, a); h8_to_f(u01, bb); h8_to_f(u10, cc); h8_to_f(u11, dd);
#pragma unroll
            for (int j = 0; j < 8; j++) {
                float vv = a[j]*w00 + bb[j]*w01 + cc[j]*w10 + dd[j]*w11;
                fs[j] += vv;
                fq[j] += vv * vv;
            }
        }
    }

    float denom = s + 1e-6f;
    float invd = 1.f / denom;
    float alpha = s * invd;
    float two_m_a = 2.f - alpha;
    __half* xo = g_xh + (size_t)gp * XPAD_H;

    if (q < 3) {
        float m  = rs * invd;
        float e2 = rq * invd;
        xo[q]      = __float2half_rn(m);
        xo[35 + q] = __float2half_rn(e2 - two_m_a * m * m);
    }
#pragma unroll
    for (int j = 0; j < 8; j++) {
        int i = 3 + q * 8 + j;
        float m  = fs[j] * invd;
        float e2 = fq[j] * invd;
        xo[i]      = __float2half_rn(m);
        xo[35 + i] = __float2half_rn(e2 - two_m_a * m * m);
    }
    if (q == 0) {
#pragma unroll
        for (int j = 70; j < XPAD_H; j++) xo[j] = __float2half_rn(0.f);
    }
}

// ---------------------------------------------------------------------------
// Kernel 2: fully-fused register-resident MLP. Persistent, 148 blocks x 256
// threads. All 5 weight layers resident in SMEM (170 KB). Each warp owns 16
// points x full N=128; layer chain lives in registers (D-frag == next A-frag).
// 2 barriers per tile. Heads from fp32 accumulators + quad shfl.
// ---------------------------------------------------------------------------
__global__ void __launch_bounds__(FF_THREADS, 1) mlp_ff_kernel(
    const float* __restrict__ b0, const float* __restrict__ b1,
    const float* __restrict__ b2, const float* __restrict__ b3,
    const float* __restrict__ b4,
    const float* __restrict__ w5, const float* __restrict__ b5,
    const float* __restrict__ dw, const float* __restrict__ db,
    float* __restrict__ out) {

    extern __shared__ char smem[];
    uint32_t* actin = reinterpret_cast<uint32_t*>(smem);                 // ACTIN_BYTES
    uint32_t* wsm   = reinterpret_cast<uint32_t*>(smem + ACTIN_BYTES);   // WS_ALL_BYTES
    float* bias = reinterpret_cast<float*>(smem + ACTIN_BYTES + WS_ALL_BYTES); // 5*128
    float* w5s  = bias + 5 * DH;   // 384
    float* dws  = w5s + DH * 3;    // 128

    const int tid  = threadIdx.x;
    const int lane = tid & 31;
    const int warp = tid >> 5;
    const int r  = lane >> 2;
    const int cp = lane & 3;
    const int R0 = warp * 16 + r;
    const int R1 = R0 + 8;

    const uint32_t s_act = smem_u32(actin);
    const uint32_t s_w   = smem_u32(wsm);

    // stage all 5 weight layers + first act tile (one cp.async group)
    for (int i = tid; i < WS_ALL_BYTES / 16; i += FF_THREADS)
        cp16(s_w + (uint32_t)i * 16, g_wpadh + i * 8);
    int tile = blockIdx.x;
    {
        const __half* gx = g_xh + (size_t)tile * TM * XPAD_H;
        for (int i = tid; i < TM * 10; i += FF_THREADS) {
            int row = i / 10, ch = i - row * 10;
            cp16(s_act + (uint32_t)(row * 336 + ch * 16),
                 gx + (size_t)row * XPAD_H + ch * 8);
        }
    }
    CP_COMMIT();

    // biases + head weights (plain loads overlap cp.async)
    if (tid < DH) {
        bias[0 * DH + tid] = b0[tid];
        bias[1 * DH + tid] = b1[tid];
        bias[2 * DH + tid] = b2[tid];
        bias[3 * DH + tid] = b3[tid];
        bias[4 * DH + tid] = b4[tid];
        dws[tid] = dw[tid];
    }
    for (int i = tid; i < DH * 3; i += FF_THREADS) w5s[i] = w5[i];
    const float db0 = db[0];
    const float b50 = b5[0], b51 = b5[1], b52 = b5[2];

    float acc[16][4];
    uint32_t h[32];

    for (; tile < NT; tile += FF_GRID) {
        CP_WAIT0();
        __syncthreads();   // act tile + (first iter) weights visible to all

        // ---- layer 0: A from actin (K=80 -> 5 ksteps) ----
#pragma unroll
        for (int j = 0; j < 16; j++)
#pragma unroll
            for (int d = 0; d < 4; d++) acc[j][d] = 0.f;
#pragma unroll
        for (int kt = 0; kt < 5; kt++) {
            uint32_t a[4];
            a[0] = actin[R0 * ACTIN_W32 + kt * 8 + cp];
            a[1] = actin[R1 * ACTIN_W32 + kt * 8 + cp];
            a[2] = actin[R0 * ACTIN_W32 + kt * 8 + 4 + cp];
            a[3] = actin[R1 * ACTIN_W32 + kt * 8 + 4 + cp];
#pragma unroll
            for (int j = 0; j < 16; j++) {
                uint32_t bfr[2];
                int bi = (j * 8 + r) * WS_W32 + kt * 8 + cp;
                bfr[0] = wsm[bi];
                bfr[1] = wsm[bi + 4];
                mma_f16(acc[j], a, bfr);
            }
        }

        // pf: bias add, sigma head partials, convert to h (fp16)
        {
            float sp0 = 0.f, sp1 = 0.f;
#pragma unroll
            for (int j = 0; j < 16; j++) {
                int c0 = j * 8 + cp * 2;
                float bv0 = bias[c0], bv1 = bias[c0 + 1];
                float v0 = acc[j][0] + bv0, v1 = acc[j][1] + bv1;
                float v2 = acc[j][2] + bv0, v3 = acc[j][3] + bv1;
                float d0 = dws[c0], d1 = dws[c0 + 1];
                sp0 = fmaf(v0, d0, fmaf(v1, d1, sp0));
                sp1 = fmaf(v2, d0, fmaf(v3, d1, sp1));
                h[j]      = pack_h2(v0, v1);
                h[16 + j] = pack_h2(v2, v3);
            }
            sp0 += __shfl_xor_sync(0xffffffff, sp0, 1);
            sp0 += __shfl_xor_sync(0xffffffff, sp0, 2);
            sp1 += __shfl_xor_sync(0xffffffff, sp1, 1);
            sp1 += __shfl_xor_sync(0xffffffff, sp1, 2);
            if (cp == 0) {
                size_t p = (size_t)tile * TM;
                out[(p + R0) * 4 + 3] = fmaxf(sp0 + db0, 0.f);
                out[(p + R1) * 4 + 3] = fmaxf(sp1 + db0, 0.f);
            }
        }

        __syncthreads();   // all warps done reading actin
        {
            int nt2 = tile + FF_GRID;
            if (nt2 < NT) {
                const __half* gx = g_xh + (size_t)nt2 * TM * XPAD_H;
                for (int i = tid; i < TM * 10; i += FF_THREADS) {
                    int row = i / 10, ch = i - row * 10;
                    cp16(s_act + (uint32_t)(row * 336 + ch * 16),
                         gx + (size_t)row * XPAD_H + ch * 8);
                }
            }
        }
        CP_COMMIT();       // overlaps layers 1..4 below

        // ---- layers 1..4 (register chain; weights resident) ----
#pragma unroll 1
        for (int l = 1; l < 5; l++) {
            const uint32_t* wp = wsm + l * WL_W32;
            const float* bl = bias + l * DH;
#pragma unroll
            for (int j = 0; j < 16; j++)
#pragma unroll
                for (int d = 0; d < 4; d++) acc[j][d] = 0.f;
#pragma unroll
            for (int kt = 0; kt < 8; kt++) {
                uint32_t a[4];
                a[0] = h[2 * kt];
                a[1] = h[16 + 2 * kt];
                a[2] = h[2 * kt + 1];
                a[3] = h[16 + 2 * kt + 1];
#pragma unroll
                for (int j = 0; j < 16; j++) {
                    uint32_t bfr[2];
                    int bi = (j * 8 + r) * WS_W32 + kt * 8 + cp;
                    bfr[0] = wp[bi];
                    bfr[1] = wp[bi + 4];
                    mma_f16(acc[j], a, bfr);
                }
            }
            if (l < 4) {
#pragma unroll
                for (int j = 0; j < 16; j++) {
                    int c0 = j * 8 + cp * 2;
                    float bv0 = bl[c0], bv1 = bl[c0 + 1];
                    float v0 = acc[j][0] + bv0, v1 = acc[j][1] + bv1;
                    float v2 = acc[j][2] + bv0, v3 = acc[j][3] + bv1;
                    v0 = v0 > 0.f ? v0 : 0.01f * v0;
                    v1 = v1 > 0.f ? v1 : 0.01f * v1;
                    v2 = v2 > 0.f ? v2 : 0.01f * v2;
                    v3 = v3 > 0.f ? v3 : 0.01f * v3;
                    h[j]      = pack_h2(v0, v1);
                    h[16 + j] = pack_h2(v2, v3);
                }
            } else {
                // final layer: leaky + rgb head from fp32, quad shfl reduce
                float ra0 = 0.f, ra1 = 0.f, ra2 = 0.f;
                float rb0 = 0.f, rb1 = 0.f, rb2 = 0.f;
#pragma unroll
                for (int j = 0; j < 16; j++) {
                    int c0 = j * 8 + cp * 2;
                    float bv0 = bl[c0], bv1 = bl[c0 + 1];
                    float v0 = acc[j][0] + bv0, v1 = acc[j][1] + bv1;
                    float v2 = acc[j][2] + bv0, v3 = acc[j][3] + bv1;
                    v0 = v0 > 0.f ? v0 : 0.01f * v0;
                    v1 = v1 > 0.f ? v1 : 0.01f * v1;
                    v2 = v2 > 0.f ? v2 : 0.01f * v2;
                    v3 = v3 > 0.f ? v3 : 0.01f * v3;
                    float w00 = w5s[c0 * 3 + 0], w01 = w5s[c0 * 3 + 1], w02 = w5s[c0 * 3 + 2];
                    float w10 = w5s[(c0 + 1) * 3 + 0], w11 = w5s[(c0 + 1) * 3 + 1], w12 = w5s[(c0 + 1) * 3 + 2];
                    ra0 = fmaf(v0, w00, fmaf(v1, w10, ra0));
                    ra1 = fmaf(v0, w01, fmaf(v1, w11, ra1));
                    ra2 = fmaf(v0, w02, fmaf(v1, w12, ra2));
                    rb0 = fmaf(v2, w00, fmaf(v3, w10, rb0));
                    rb1 = fmaf(v2, w01, fmaf(v3, w11, rb1));
                    rb2 = fmaf(v2, w02, fmaf(v3, w12, rb2));
                }
                ra0 += __shfl_xor_sync(0xffffffff, ra0, 1);
                ra0 += __shfl_xor_sync(0xffffffff, ra0, 2);
                ra1 += __shfl_xor_sync(0xffffffff, ra1, 1);
                ra1 += __shfl_xor_sync(0xffffffff, ra1, 2);
                ra2 += __shfl_xor_sync(0xffffffff, ra2, 1);
                ra2 += __shfl_xor_sync(0xffffffff, ra2, 2);
                rb0 += __shfl_xor_sync(0xffffffff, rb0, 1);
                rb0 += __shfl_xor_sync(0xffffffff, rb0, 2);
                rb1 += __shfl_xor_sync(0xffffffff, rb1, 1);
                rb1 += __shfl_xor_sync(0xffffffff, rb1, 2);
                rb2 += __shfl_xor_sync(0xffffffff, rb2, 1);
                rb2 += __shfl_xor_sync(0xffffffff, rb2, 2);
                if (cp == 0) {
                    size_t p = (size_t)tile * TM;
                    size_t o0 = (p + R0) * 4, o1 = (p + R1) * 4;
                    out[o0 + 0] = tanhf(ra0 + b50);
                    out[o0 + 1] = tanhf(ra1 + b51);
                    out[o0 + 2] = tanhf(ra2 + b52);
                    out[o1 + 0] = tanhf(rb0 + b50);
                    out[o1 + 1] = tanhf(rb1 + b51);
                    out[o1 + 2] = tanhf(rb2 + b52);
                }
            }
        }
    }
}

// ---------------------------------------------------------------------------
// Launch
// ---------------------------------------------------------------------------
extern "C" void kernel_launch(void* const* d_in, const int* in_sizes, int n_in,
                              void* d_out, int out_size) {
    const float* xyz       = (const float*)d_in[0];
    const float* src_imgs  = (const float*)d_in[2];
    const float* src_cams  = (const float*)d_in[3];
    const float* src_feats = (const float*)d_in[4];
    const float* w0 = (const float*)d_in[5];
    const float* b0 = (const float*)d_in[6];
    const float* w1 = (const float*)d_in[7];
    const float* b1 = (const float*)d_in[8];
    const float* w2 = (const float*)d_in[9];
    const float* b2 = (const float*)d_in[10];
    const float* w3 = (const float*)d_in[11];
    const float* b3 = (const float*)d_in[12];
    const float* w4 = (const float*)d_in[13];
    const float* b4 = (const float*)d_in[14];
    const float* w5 = (const float*)d_in[15];
    const float* b5 = (const float*)d_in[16];
    const float* dw = (const float*)d_in[17];
    const float* db = (const float*)d_in[18];
    float* out = (float*)d_out;

    const int smem_bytes = ACTIN_BYTES + WS_ALL_BYTES
                         + (5 * DH + DH * 3 + DH) * (int)sizeof(float);
    cudaFuncSetAttribute(mlp_ff_kernel,
                         cudaFuncAttributeMaxDynamicSharedMemorySize, smem_bytes);

    proj_kernel<<<1, 32>>>(src_cams);
    wprep_kernel<<<(5 * 128 * WS_W + 255) / 256, 256>>>(w0, w1, w2, w3, w4);
    tfeat_kernel<<<(B_ * NV * H1_ * W1_ * D_) / 256, 256>>>(src_feats);
    timg_kernel<<<(B_ * NV * H_ * W_ * 3 + 255) / 256, 256>>>(src_imgs);
    featurize_kernel<<<(PT * 4) / 256, 256>>>(xyz);
    mlp_ff_kernel<<<FF_GRID, FF_THREADS, smem_bytes>>>(b0, b1, b2, b3, b4,
                                                       w5, b5, dw, db, out);
}

// round 13
// speedup vs baseline: 1.3064x; 1.0148x over previous
// Resubmission of the round-12 kernel: the previous bench died with the
// broker-level "GB300 container failed twice" error (same class as rounds 0/6,
// which resolved on retry). The kernel was never compiled or executed;
// resubmitting unchanged to preserve attribution for the 16-warp change.
#include <cuda_runtime.h>
#include <cuda_fp16.h>
#include <math.h>
#include <stdint.h>

// ---------------------------------------------------------------------------
// Problem constants
// ---------------------------------------------------------------------------
#define B_ 2
#define NV 4
#define H_ 240
#define W_ 240
#define H1_ 120
#define W1_ 120
#define D_ 32
#define NPB 131072
#define PT (B_ * NPB)
#define INBASE 70
#define XPAD_H 80             // padded fp16 feature row (160 B)
#define DH 128
#define TM 256                // points per tile (16 warps x 16 rows)
#define NT (PT / TM)          // 1024 tiles
#define FF_GRID 148
#define FF_THREADS 512        // 16 warps

#define WS_W 136              // halves per weight row [n][k] (272 B, conflict-free)
#define WS_W32 68
#define WL_W32 (128 * WS_W32)
#define WS_ALL_BYTES (5 * 128 * WS_W * 2)  // 174080

#define ACTIN_W32 44          // words per act-in row (176 B; bank = 12r+cp, conflict-free)
#define ACTIN_BYTES (TM * ACTIN_W32 * 4)   // 45056

// ---------------------------------------------------------------------------
// Scratch (device globals)
// ---------------------------------------------------------------------------
__device__ __half g_xh[(size_t)PT * XPAD_H];
__device__ __half g_featsTh[(size_t)B_ * NV * H1_ * W1_ * D_];
__device__ __half g_imgsTh[(size_t)B_ * NV * H_ * W_ * 3];
__device__ float  g_proj[B_ * NV * 12];
__device__ __half g_wpadh[5 * 128 * WS_W];

// ---------------------------------------------------------------------------
// helpers
// ---------------------------------------------------------------------------
__device__ __forceinline__ void mma_f16(float (&d)[4], const uint32_t (&a)[4],
                                        const uint32_t (&b)[2]) {
    asm volatile(
        "mma.sync.aligned.m16n8k16.row.col.f32.f16.f16.f32 "
        "{%0,%1,%2,%3}, {%4,%5,%6,%7}, {%8,%9}, {%0,%1,%2,%3};"
        : "+f"(d[0]), "+f"(d[1]), "+f"(d[2]), "+f"(d[3])
        : "r"(a[0]), "r"(a[1]), "r"(a[2]), "r"(a[3]), "r"(b[0]), "r"(b[1]));
}

__device__ __forceinline__ uint32_t smem_u32(const void* p) {
    return (uint32_t)__cvta_generic_to_shared(p);
}

__device__ __forceinline__ void cp16(uint32_t saddr, const void* g) {
    asm volatile("cp.async.cg.shared.global [%0], [%1], 16;" :: "r"(saddr), "l"(g));
}
#define CP_COMMIT() asm volatile("cp.async.commit_group;")
#define CP_WAIT0()  asm volatile("cp.async.wait_group 0;")

__device__ __forceinline__ uint32_t pack_h2(float x, float y) {
    __half2 h = __halves2half2(__float2half_rn(x), __float2half_rn(y));
    return *reinterpret_cast<uint32_t*>(&h);
}

__device__ __forceinline__ void h8_to_f(const uint4& u, float* f) {
    const __half2* h = reinterpret_cast<const __half2*>(&u);
#pragma unroll
    for (int i = 0; i < 4; i++) {
        float2 v = __half22float2(h[i]);
        f[i * 2 + 0] = v.x;
        f[i * 2 + 1] = v.y;
    }
}

// ---------------------------------------------------------------------------
// Kernel 0: projection matrices  P = K @ inv(c2w)[0:3, :]
// ---------------------------------------------------------------------------
__global__ void proj_kernel(const float* __restrict__ cams) {
    int i = threadIdx.x;
    if (i >= B_ * NV) return;
    const float* c = cams + i * 27;
    float K[9];
#pragma unroll
    for (int j = 0; j < 9; j++) K[j] = c[2 + j];
    float m[16];
#pragma unroll
    for (int j = 0; j < 16; j++) m[j] = c[11 + j];

    float inv[16];
    inv[0]  =  m[5]*m[10]*m[15] - m[5]*m[11]*m[14] - m[9]*m[6]*m[15] + m[9]*m[7]*m[14] + m[13]*m[6]*m[11] - m[13]*m[7]*m[10];
    inv[4]  = -m[4]*m[10]*m[15] + m[4]*m[11]*m[14] + m[8]*m[6]*m[15] - m[8]*m[7]*m[14] - m[12]*m[6]*m[11] + m[12]*m[7]*m[10];
    inv[8]  =  m[4]*m[9]*m[15]  - m[4]*m[11]*m[13] - m[8]*m[5]*m[15] + m[8]*m[7]*m[13] + m[12]*m[5]*m[11] - m[12]*m[7]*m[9];
    inv[12] = -m[4]*m[9]*m[14]  + m[4]*m[10]*m[13] + m[8]*m[5]*m[14] - m[8]*m[6]*m[13] - m[12]*m[5]*m[10] + m[12]*m[6]*m[9];
    inv[1]  = -m[1]*m[10]*m[15] + m[1]*m[11]*m[14] + m[9]*m[2]*m[15] - m[9]*m[3]*m[14] - m[13]*m[2]*m[11] + m[13]*m[3]*m[10];
    inv[5]  =  m[0]*m[10]*m[15] - m[0]*m[11]*m[14] - m[8]*m[2]*m[15] + m[8]*m[3]*m[14] + m[12]*m[2]*m[11] - m[12]*m[3]*m[10];
    inv[9]  = -m[0]*m[9]*m[15]  + m[0]*m[11]*m[13] + m[8]*m[1]*m[15] - m[8]*m[3]*m[13] - m[12]*m[1]*m[11] + m[12]*m[3]*m[9];
    inv[13] =  m[0]*m[9]*m[14]  - m[0]*m[10]*m[13] - m[8]*m[1]*m[14] + m[8]*m[2]*m[13] + m[12]*m[1]*m[10] - m[12]*m[2]*m[9];
    inv[2]  =  m[1]*m[6]*m[15]  - m[1]*m[7]*m[14]  - m[5]*m[2]*m[15] + m[5]*m[3]*m[14] + m[13]*m[2]*m[7]  - m[13]*m[3]*m[6];
    inv[6]  = -m[0]*m[6]*m[15]  + m[0]*m[7]*m[14]  + m[4]*m[2]*m[15] - m[4]*m[3]*m[14] - m[12]*m[2]*m[7]  + m[12]*m[3]*m[6];
    inv[10] =  m[0]*m[5]*m[15]  - m[0]*m[7]*m[13]  - m[4]*m[1]*m[15] + m[4]*m[3]*m[13] + m[12]*m[1]*m[7]  - m[12]*m[3]*m[5];
    inv[14] = -m[0]*m[5]*m[14]  + m[0]*m[6]*m[13]  + m[4]*m[1]*m[14] - m[4]*m[2]*m[13] - m[12]*m[1]*m[6]  + m[12]*m[2]*m[5];
    inv[3]  = -m[1]*m[6]*m[11]  + m[1]*m[7]*m[10]  + m[5]*m[2]*m[11] - m[5]*m[3]*m[10] - m[9]*m[2]*m[7]   + m[9]*m[3]*m[6];
    inv[7]  =  m[0]*m[6]*m[11]  - m[0]*m[7]*m[10]  - m[4]*m[2]*m[11] + m[4]*m[3]*m[10] + m[8]*m[2]*m[7]   - m[8]*m[3]*m[6];
    inv[11] = -m[0]*m[5]*m[11]  + m[0]*m[7]*m[9]   + m[4]*m[1]*m[11] - m[4]*m[3]*m[9]  - m[8]*m[1]*m[7]   + m[8]*m[3]*m[5];
    inv[15] =  m[0]*m[5]*m[10]  - m[0]*m[6]*m[9]   - m[4]*m[1]*m[10] + m[4]*m[2]*m[9]  + m[8]*m[1]*m[6]   - m[8]*m[2]*m[5];

    float det = m[0]*inv[0] + m[1]*inv[4] + m[2]*inv[8] + m[3]*inv[12];
    float id = 1.0f / det;
#pragma unroll
    for (int j = 0; j < 16; j++) inv[j] *= id;

#pragma unroll
    for (int r = 0; r < 3; r++) {
#pragma unroll
        for (int cc = 0; cc < 4; cc++) {
            float s = K[r*3+0]*inv[0*4+cc] + K[r*3+1]*inv[1*4+cc] + K[r*3+2]*inv[2*4+cc];
            g_proj[i*12 + r*4 + cc] = s;
        }
    }
}

// ---------------------------------------------------------------------------
// Weight prep: fp16, transposed [l][n][k]
// ---------------------------------------------------------------------------
__global__ void wprep_kernel(const float* __restrict__ w0, const float* __restrict__ w1,
                             const float* __restrict__ w2, const float* __restrict__ w3,
                             const float* __restrict__ w4) {
    int o = blockIdx.x * blockDim.x + threadIdx.x;
    if (o >= 5 * 128 * WS_W) return;
    int l = o / (128 * WS_W);
    int rem = o - l * 128 * WS_W;
    int n = rem / WS_W;
    int k = rem - n * WS_W;
    float v = 0.f;
    if (l == 0) {
        if (k < INBASE) v = w0[k * DH + n];
    } else if (k < DH) {
        const float* w = (l == 1) ? w1 : (l == 2) ? w2 : (l == 3) ? w3 : w4;
        v = w[k * DH + n];
    }
    g_wpadh[o] = __float2half_rn(v);
}

// ---------------------------------------------------------------------------
// Transposes to channel-last fp16
// ---------------------------------------------------------------------------
__global__ void tfeat_kernel(const float* __restrict__ f) {
    int o = blockIdx.x * blockDim.x + threadIdx.x;
    if (o >= B_ * NV * H1_ * W1_ * D_) return;
    int c = o & (D_ - 1);
    int rest = o >> 5;
    int x = rest % W1_;
    int t2 = rest / W1_;
    int y = t2 % H1_;
    int bv = t2 / H1_;
    g_featsTh[o] = __float2half_rn(f[((size_t)(bv * D_ + c)) * (H1_ * W1_) + y * W1_ + x]);
}

__global__ void timg_kernel(const float* __restrict__ im) {
    int o = blockIdx.x * blockDim.x + threadIdx.x;
    if (o >= B_ * NV * H_ * W_ * 3) return;
    int c = o % 3;
    int rest = o / 3;
    int x = rest % W_;
    int t2 = rest / W_;
    int y = t2 % H_;
    int bv = t2 / H_;
    g_imgsTh[o] = __float2half_rn(im[((size_t)(bv * 3 + c)) * (H_ * W_) + y * W_ + x]);
}

// ---------------------------------------------------------------------------
// Kernel 1: quad featurize (4 threads/point), fp16 taps -> g_xh [PT][80]
// ---------------------------------------------------------------------------
__global__ void __launch_bounds__(256) featurize_kernel(const float* __restrict__ xyz) {
    int t = blockIdx.x * blockDim.x + threadIdx.x;
    int gp = t >> 2;
    int q  = t & 3;
    if (gp >= PT) return;
    int b = gp / NPB;

    float X = xyz[(size_t)gp * 3 + 0];
    float Y = xyz[(size_t)gp * 3 + 1];
    float Z = xyz[(size_t)gp * 3 + 2];

    float fs[8], fq[8];
#pragma unroll
    for (int i = 0; i < 8; i++) { fs[i] = 0.f; fq[i] = 0.f; }
    float rs = 0.f, rq = 0.f;
    float s = 0.f;

    const float SX = (float)(W1_ - 1) / (float)(W_ - 1);
    const float SY = (float)(H1_ - 1) / (float)(H_ - 1);

#pragma unroll
    for (int v = 0; v < NV; v++) {
        const float* Pm = &g_proj[(b * NV + v) * 12];
        float pxn = Pm[0]*X + Pm[1]*Y + Pm[2]*Z  + Pm[3];
        float pyn = Pm[4]*X + Pm[5]*Y + Pm[6]*Z  + Pm[7];
        float pz  = Pm[8]*X + Pm[9]*Y + Pm[10]*Z + Pm[11];
        float d = fmaxf(pz, 1e-8f);
        float px = pxn / d;
        float py = pyn / d;
        bool inb = (pz > 1e-4f) && (px >= 0.f) && (px <= (float)(W_ - 1))
                                && (py >= 0.f) && (py <= (float)(H_ - 1));
        if (!inb) continue;
        s += 1.f;

        if (q < 3) {
            float x0f = floorf(px), y0f = floorf(py);
            float wx = px - x0f, wy = py - y0f;
            int x0 = (int)x0f;
            int y0 = (int)y0f;
            int x1 = min(x0 + 1, W_ - 1);
            int y1 = min(y0 + 1, H_ - 1);
            float w00 = (1.f - wx) * (1.f - wy);
            float w01 = wx * (1.f - wy);
            float w10 = (1.f - wx) * wy;
            float w11 = wx * wy;
            const __half* ib = g_imgsTh + (size_t)(b * NV + v) * H_ * W_ * 3 + q;
            float val = __half2float(ib[(size_t)(y0 * W_ + x0) * 3]) * w00
                      + __half2float(ib[(size_t)(y0 * W_ + x1) * 3]) * w01
                      + __half2float(ib[(size_t)(y1 * W_ + x0) * 3]) * w10
                      + __half2float(ib[(size_t)(y1 * W_ + x1) * 3]) * w11;
            rs += val;
            rq += val * val;
        }

        {
            float fx = px * SX;
            float fy = py * SY;
            float x0f = floorf(fx), y0f = floorf(fy);
            float wx = fx - x0f, wy = fy - y0f;
            int x0 = (int)x0f;
            int y0 = (int)y0f;
            int x1 = min(x0 + 1, W1_ - 1);
            int y1 = min(y0 + 1, H1_ - 1);
            float w00 = (1.f - wx) * (1.f - wy);
            float w01 = wx * (1.f - wy);
            float w10 = (1.f - wx) * wy;
            float w11 = wx * wy;
            const __half* fb = g_featsTh + (size_t)(b * NV + v) * H1_ * W1_ * D_ + q * 8;
            uint4 u00 = *reinterpret_cast<const uint4*>(fb + (size_t)(y0 * W1_ + x0) * D_);
            uint4 u01 = *reinterpret_cast<const uint4*>(fb + (size_t)(y0 * W1_ + x1) * D_);
            uint4 u10 = *reinterpret_cast<const uint4*>(fb + (size_t)(y1 * W1_ + x0) * D_);
            uint4 u11 = *reinterpret_cast<const uint4*>(fb + (size_t)(y1 * W1_ + x1) * D_);
            float a[8], bb[8], cc[8], dd[8];
            h8_to_f(u00, a); h8_to_f(u01, bb); h8_to_f(u10, cc); h8_to_f(u11, dd);
#pragma unroll
            for (int j = 0; j < 8; j++) {
                float vv = a[j]*w00 + bb[j]*w01 + cc[j]*w10 + dd[j]*w11;
                fs[j] += vv;
                fq[j] += vv * vv;
            }
        }
    }

    float denom = s + 1e-6f;
    float invd = 1.f / denom;
    float alpha = s * invd;
    float two_m_a = 2.f - alpha;
    __half* xo = g_xh + (size_t)gp * XPAD_H;

    if (q < 3) {
        float m  = rs * invd;
        float e2 = rq * invd;
        xo[q]      = __float2half_rn(m);
        xo[35 + q] = __float2half_rn(e2 - two_m_a * m * m);
    }
#pragma unroll
    for (int j = 0; j < 8; j++) {
        int i = 3 + q * 8 + j;
        float m  = fs[j] * invd;
        float e2 = fq[j] * invd;
        xo[i]      = __float2half_rn(m);
        xo[35 + i] = __float2half_rn(e2 - two_m_a * m * m);
    }
    if (q == 0) {
#pragma unroll
        for (int j = 70; j < XPAD_H; j++) xo[j] = __float2half_rn(0.f);
    }
}

// ---------------------------------------------------------------------------
// Kernel 2: fully-fused register-resident MLP. Persistent, 148 blocks x 512
// threads (16 warps = 4/SMSP). Tile = 256 points; each warp owns 16 rows x
// full N=128 in registers; all 5 weight layers resident in SMEM.
// ---------------------------------------------------------------------------
__global__ void __launch_bounds__(FF_THREADS, 1) mlp_ff_kernel(
    const float* __restrict__ b0, const float* __restrict__ b1,
    const float* __restrict__ b2, const float* __restrict__ b3,
    const float* __restrict__ b4,
    const float* __restrict__ w5, const float* __restrict__ b5,
    const float* __restrict__ dw, const float* __restrict__ db,
    float* __restrict__ out) {

    extern __shared__ char smem[];
    uint32_t* actin = reinterpret_cast<uint32_t*>(smem);                 // ACTIN_BYTES
    uint32_t* wsm   = reinterpret_cast<uint32_t*>(smem + ACTIN_BYTES);   // WS_ALL_BYTES
    float* bias = reinterpret_cast<float*>(smem + ACTIN_BYTES + WS_ALL_BYTES);
    float* w5s  = bias + 5 * DH;
    float* dws  = w5s + DH * 3;

    const int tid  = threadIdx.x;
    const int lane = tid & 31;
    const int warp = tid >> 5;
    const int r  = lane >> 2;
    const int cp = lane & 3;
    const int R0 = warp * 16 + r;
    const int R1 = R0 + 8;

    const uint32_t s_act = smem_u32(actin);
    const uint32_t s_w   = smem_u32(wsm);

    // stage all 5 weight layers + first act tile
    for (int i = tid; i < WS_ALL_BYTES / 16; i += FF_THREADS)
        cp16(s_w + (uint32_t)i * 16, g_wpadh + i * 8);
    int tile = blockIdx.x;
    {
        const __half* gx = g_xh + (size_t)tile * TM * XPAD_H;
        for (int i = tid; i < TM * 10; i += FF_THREADS) {
            int row = i / 10, ch = i - row * 10;
            cp16(s_act + (uint32_t)(row * (ACTIN_W32 * 4) + ch * 16),
                 gx + (size_t)row * XPAD_H + ch * 8);
        }
    }
    CP_COMMIT();

    if (tid < DH) {
        bias[0 * DH + tid] = b0[tid];
        bias[1 * DH + tid] = b1[tid];
        bias[2 * DH + tid] = b2[tid];
        bias[3 * DH + tid] = b3[tid];
        bias[4 * DH + tid] = b4[tid];
        dws[tid] = dw[tid];
    }
    for (int i = tid; i < DH * 3; i += FF_THREADS) w5s[i] = w5[i];
    const float db0 = db[0];
    const float b50 = b5[0], b51 = b5[1], b52 = b5[2];

    float acc[16][4];
    uint32_t h[32];

    for (; tile < NT; tile += FF_GRID) {
        CP_WAIT0();
        __syncthreads();

        // ---- layer 0: A from actin (K=80 -> 5 ksteps) ----
#pragma unroll
        for (int j = 0; j < 16; j++)
#pragma unroll
            for (int d = 0; d < 4; d++) acc[j][d] = 0.f;
#pragma unroll
        for (int kt = 0; kt < 5; kt++) {
            uint32_t a[4];
            a[0] = actin[R0 * ACTIN_W32 + kt * 8 + cp];
            a[1] = actin[R1 * ACTIN_W32 + kt * 8 + cp];
            a[2] = actin[R0 * ACTIN_W32 + kt * 8 + 4 + cp];
            a[3] = actin[R1 * ACTIN_W32 + kt * 8 + 4 + cp];
#pragma unroll
            for (int j = 0; j < 16; j++) {
                uint32_t bfr[2];
                int bi = (j * 8 + r) * WS_W32 + kt * 8 + cp;
                bfr[0] = wsm[bi];
                bfr[1] = wsm[bi + 4];
                mma_f16(acc[j], a, bfr);
            }
        }

        // pf: bias, sigma head partials, convert to h
        {
            float sp0 = 0.f, sp1 = 0.f;
#pragma unroll
            for (int j = 0; j < 16; j++) {
                int c0 = j * 8 + cp * 2;
                float bv0 = bias[c0], bv1 = bias[c0 + 1];
                float v0 = acc[j][0] + bv0, v1 = acc[j][1] + bv1;
                float v2 = acc[j][2] + bv0, v3 = acc[j][3] + bv1;
                float d0 = dws[c0], d1 = dws[c0 + 1];
                sp0 = fmaf(v0, d0, fmaf(v1, d1, sp0));
                sp1 = fmaf(v2, d0, fmaf(v3, d1, sp1));
                h[j]      = pack_h2(v0, v1);
                h[16 + j] = pack_h2(v2, v3);
            }
            sp0 += __shfl_xor_sync(0xffffffff, sp0, 1);
            sp0 += __shfl_xor_sync(0xffffffff, sp0, 2);
            sp1 += __shfl_xor_sync(0xffffffff, sp1, 1);
            sp1 += __shfl_xor_sync(0xffffffff, sp1, 2);
            if (cp == 0) {
                size_t p = (size_t)tile * TM;
                out[(p + R0) * 4 + 3] = fmaxf(sp0 + db0, 0.f);
                out[(p + R1) * 4 + 3] = fmaxf(sp1 + db0, 0.f);
            }
        }

        __syncthreads();   // all warps done reading actin
        {
            int nt2 = tile + FF_GRID;
            if (nt2 < NT) {
                const __half* gx = g_xh + (size_t)nt2 * TM * XPAD_H;
                for (int i = tid; i < TM * 10; i += FF_THREADS) {
                    int row = i / 10, ch = i - row * 10;
                    cp16(s_act + (uint32_t)(row * (ACTIN_W32 * 4) + ch * 16),
                         gx + (size_t)row * XPAD_H + ch * 8);
                }
            }
        }
        CP_COMMIT();

        // ---- layers 1..4 ----
#pragma unroll 1
        for (int l = 1; l < 5; l++) {
            const uint32_t* wp = wsm + l * WL_W32;
            const float* bl = bias + l * DH;
#pragma unroll
            for (int j = 0; j < 16; j++)
#pragma unroll
                for (int d = 0; d < 4; d++) acc[j][d] = 0.f;
#pragma unroll
            for (int kt = 0; kt < 8; kt++) {
                uint32_t a[4];
                a[0] = h[2 * kt];
                a[1] = h[16 + 2 * kt];
                a[2] = h[2 * kt + 1];
                a[3] = h[16 + 2 * kt + 1];
#pragma unroll
                for (int j = 0; j < 16; j++) {
                    uint32_t bfr[2];
                    int bi = (j * 8 + r) * WS_W32 + kt * 8 + cp;
                    bfr[0] = wp[bi];
                    bfr[1] = wp[bi + 4];
                    mma_f16(acc[j], a, bfr);
                }
            }
            if (l < 4) {
#pragma unroll
                for (int j = 0; j < 16; j++) {
                    int c0 = j * 8 + cp * 2;
                    float bv0 = bl[c0], bv1 = bl[c0 + 1];
                    float v0 = acc[j][0] + bv0, v1 = acc[j][1] + bv1;
                    float v2 = acc[j][2] + bv0, v3 = acc[j][3] + bv1;
                    v0 = v0 > 0.f ? v0 : 0.01f * v0;
                    v1 = v1 > 0.f ? v1 : 0.01f * v1;
                    v2 = v2 > 0.f ? v2 : 0.01f * v2;
                    v3 = v3 > 0.f ? v3 : 0.01f * v3;
                    h[j]      = pack_h2(v0, v1);
                    h[16 + j] = pack_h2(v2, v3);
                }
            } else {
                float ra0 = 0.f, ra1 = 0.f, ra2 = 0.f;
                float rb0 = 0.f, rb1 = 0.f, rb2 = 0.f;
#pragma unroll
                for (int j = 0; j < 16; j++) {
                    int c0 = j * 8 + cp * 2;
                    float bv0 = bl[c0], bv1 = bl[c0 + 1];
                    float v0 = acc[j][0] + bv0, v1 = acc[j][1] + bv1;
                    float v2 = acc[j][2] + bv0, v3 = acc[j][3] + bv1;
                    v0 = v0 > 0.f ? v0 : 0.01f * v0;
                    v1 = v1 > 0.f ? v1 : 0.01f * v1;
                    v2 = v2 > 0.f ? v2 : 0.01f * v2;
                    v3 = v3 > 0.f ? v3 : 0.01f * v3;
                    float w00 = w5s[c0 * 3 + 0], w01 = w5s[c0 * 3 + 1], w02 = w5s[c0 * 3 + 2];
                    float w10 = w5s[(c0 + 1) * 3 + 0], w11 = w5s[(c0 + 1) * 3 + 1], w12 = w5s[(c0 + 1) * 3 + 2];
                    ra0 = fmaf(v0, w00, fmaf(v1, w10, ra0));
                    ra1 = fmaf(v0, w01, fmaf(v1, w11, ra1));
                    ra2 = fmaf(v0, w02, fmaf(v1, w12, ra2));
                    rb0 = fmaf(v2, w00, fmaf(v3, w10, rb0));
                    rb1 = fmaf(v2, w01, fmaf(v3, w11, rb1));
                    rb2 = fmaf(v2, w02, fmaf(v3, w12, rb2));
                }
                ra0 += __shfl_xor_sync(0xffffffff, ra0, 1);
                ra0 += __shfl_xor_sync(0xffffffff, ra0, 2);
                ra1 += __shfl_xor_sync(0xffffffff, ra1, 1);
                ra1 += __shfl_xor_sync(0xffffffff, ra1, 2);
                ra2 += __shfl_xor_sync(0xffffffff, ra2, 1);
                ra2 += __shfl_xor_sync(0xffffffff, ra2, 2);
                rb0 += __shfl_xor_sync(0xffffffff, rb0, 1);
                rb0 += __shfl_xor_sync(0xffffffff, rb0, 2);
                rb1 += __shfl_xor_sync(0xffffffff, rb1, 1);
                rb1 += __shfl_xor_sync(0xffffffff, rb1, 2);
                rb2 += __shfl_xor_sync(0xffffffff, rb2, 1);
                rb2 += __shfl_xor_sync(0xffffffff, rb2, 2);
                if (cp == 0) {
                    size_t p = (size_t)tile * TM;
                    size_t o0 = (p + R0) * 4, o1 = (p + R1) * 4;
                    out[o0 + 0] = tanhf(ra0 + b50);
                    out[o0 + 1] = tanhf(ra1 + b51);
                    out[o0 + 2] = tanhf(ra2 + b52);
                    out[o1 + 0] = tanhf(rb0 + b50);
                    out[o1 + 1] = tanhf(rb1 + b51);
                    out[o1 + 2] = tanhf(rb2 + b52);
                }
            }
        }
    }
}

// ---------------------------------------------------------------------------
// Launch
// ---------------------------------------------------------------------------
extern "C" void kernel_launch(void* const* d_in, const int* in_sizes, int n_in,
                              void* d_out, int out_size) {
    const float* xyz       = (const float*)d_in[0];
    const float* src_imgs  = (const float*)d_in[2];
    const float* src_cams  = (const float*)d_in[3];
    const float* src_feats = (const float*)d_in[4];
    const float* w0 = (const float*)d_in[5];
    const float* b0 = (const float*)d_in[6];
    const float* w1 = (const float*)d_in[7];
    const float* b1 = (const float*)d_in[8];
    const float* w2 = (const float*)d_in[9];
    const float* b2 = (const float*)d_in[10];
    const float* w3 = (const float*)d_in[11];
    const float* b3 = (const float*)d_in[12];
    const float* w4 = (const float*)d_in[13];
    const float* b4 = (const float*)d_in[14];
    const float* w5 = (const float*)d_in[15];
    const float* b5 = (const float*)d_in[16];
    const float* dw = (const float*)d_in[17];
    const float* db = (const float*)d_in[18];
    float* out = (float*)d_out;

    const int smem_bytes = ACTIN_BYTES + WS_ALL_BYTES
                         + (5 * DH + DH * 3 + DH) * (int)sizeof(float);
    cudaFuncSetAttribute(mlp_ff_kernel,
                         cudaFuncAttributeMaxDynamicSharedMemorySize, smem_bytes);

    proj_kernel<<<1, 32>>>(src_cams);
    wprep_kernel<<<(5 * 128 * WS_W + 255) / 256, 256>>>(w0, w1, w2, w3, w4);
    tfeat_kernel<<<(B_ * NV * H1_ * W1_ * D_) / 256, 256>>>(src_feats);
    timg_kernel<<<(B_ * NV * H_ * W_ * 3 + 255) / 256, 256>>>(src_imgs);
    featurize_kernel<<<(PT * 4) / 256, 256>>>(xyz);
    mlp_ff_kernel<<<FF_GRID, FF_THREADS, smem_bytes>>>(b0, b1, b2, b3, b4,
                                                       w5, b5, dw, db, out);
}